// round 10
// baseline (speedup 1.0000x reference)
#include <cuda_runtime.h>
#include <cstdint>

#define BATCH 64
#define SEQ   512
#define EMB   128
#define HID   256
#define G4    1024            // 4*HID
#define NTAGS 50
#define M_ROWS (BATCH*SEQ)    // 32768
#define REC_BLOCKS 128        // 2 dirs * 32 j-slices * 2 batch-halves
#define GRP_BLOCKS 32         // blocks per (dir, bhalf) barrier group
#define NBARW 8               // distributed arrival words per group (32B apart)

// ---------------- scratch (device globals; allocation-free) ----------------
__device__ float g_x   [(size_t)M_ROWS*EMB];
__device__ float g_xg_f[(size_t)M_ROWS*G4];
__device__ float g_xg_b[(size_t)M_ROWS*G4];
__device__ float g_o1  [(size_t)M_ROWS*2*HID];
__device__ float g_o2  [(size_t)M_ROWS*2*HID];
__device__ float g_h1  [2][2][HID][BATCH];        // [parity][dir][k][b]
__device__ float g_h2  [2][2][HID][BATCH];
__device__ int   g_bar [2][SEQ][4][NBARW][8];     // [layer][step][group][word][pad 32B]

// ---------------- helpers ----------------
__device__ __forceinline__ int ld_relaxed(const int* p) {
    int v;
    asm volatile("ld.relaxed.gpu.global.b32 %0, [%1];" : "=r"(v) : "l"(p));
    return v;
}
__device__ __forceinline__ void fence_acq() {
    asm volatile("fence.acq_rel.gpu;" ::: "memory");
}
__device__ __forceinline__ void red_release_add(int* p, int v) {
    asm volatile("red.release.gpu.global.add.u32 [%0], %1;" :: "l"(p), "r"(v) : "memory");
}
__device__ __forceinline__ float sigf(float x)  { return 1.f/(1.f + __expf(-x)); }
__device__ __forceinline__ float tanhf_(float x){ return 1.f - 2.f/(__expf(2.f*x) + 1.f); }
__device__ __forceinline__ uint32_t f2tf32(float f) {
    uint32_t u;
    asm("cvt.rna.tf32.f32 %0, %1;" : "=r"(u) : "f"(f));
    return u;
}
__device__ __forceinline__ void mma_tf32(float& c0, float& c1, float& c2, float& c3,
                                         uint32_t a0, uint32_t a1, uint32_t a2, uint32_t a3,
                                         uint32_t b0, uint32_t b1) {
    asm volatile("mma.sync.aligned.m16n8k8.row.col.f32.tf32.tf32.f32 "
                 "{%0,%1,%2,%3}, {%4,%5,%6,%7}, {%8,%9}, {%0,%1,%2,%3};"
                 : "+f"(c0), "+f"(c1), "+f"(c2), "+f"(c3)
                 : "r"(a0), "r"(a1), "r"(a2), "r"(a3), "r"(b0), "r"(b1));
}

// ---------------- init ----------------
__global__ void init_kernel() {
    int i = blockIdx.x * blockDim.x + threadIdx.x;    // 262144 threads
    if (i < 2*2*HID*BATCH) {
        (&g_h1[0][0][0][0])[i] = 0.f;
        (&g_h2[0][0][0][0])[i] = 0.f;
    }
    if (i < 2*SEQ*4*NBARW*8) (&g_bar[0][0][0][0][0])[i] = 0;
}

// ---------------- embedding ----------------
__global__ void embed_kernel(const int* __restrict__ words, const float* __restrict__ emb) {
    int row = blockIdx.x * 8 + (threadIdx.x >> 5);
    int lane = threadIdx.x & 31;
    int w = words[row];
    const float4* src = (const float4*)(emb + (size_t)w * EMB);
    float4*       dst = (float4*)(g_x + (size_t)row * EMB);
    dst[lane] = src[lane];
}

// ---------------- tf32 tensor-core dual GEMM (unchanged) ----------------
__global__ __launch_bounds__(256) void gemm_tf32_dual(
    const float* __restrict__ A,
    const float* __restrict__ Bw_f, const float* __restrict__ Bw_b,
    const float* __restrict__ b1f, const float* __restrict__ b2f,
    const float* __restrict__ b1b, const float* __restrict__ b2b,
    float* __restrict__ Cf, float* __restrict__ Cb,
    int M, int N, int K)
{
    const float* Bw    = blockIdx.z ? Bw_b : Bw_f;
    const float* bias1 = blockIdx.z ? b1b  : b1f;
    const float* bias2 = blockIdx.z ? b2b  : b2f;
    float*       C     = blockIdx.z ? Cb   : Cf;

    __shared__ uint32_t As[2][128][20];
    __shared__ uint32_t Bs[2][128][20];

    const int tid  = threadIdx.x;
    const int lane = tid & 31;
    const int warp = tid >> 5;
    const int m0 = blockIdx.y * 128;
    const int n0 = blockIdx.x * 128;
    const int wm = (warp >> 2) * 64;
    const int wn = (warp & 3) * 32;
    const int ar = lane >> 2;
    const int ac = lane & 3;

    const int lr = tid >> 2;
    const int lk = (tid & 3) * 4;
    const float* Aptr0 = A  + (size_t)(m0 + lr)      * K + lk;
    const float* Aptr1 = A  + (size_t)(m0 + 64 + lr) * K + lk;
    const float* Bptr0 = Bw + (size_t)(n0 + lr)      * K + lk;
    const float* Bptr1 = Bw + (size_t)(n0 + 64 + lr) * K + lk;

    float c[4][4][4];
    #pragma unroll
    for (int i = 0; i < 4; i++)
        #pragma unroll
        for (int j = 0; j < 4; j++)
            #pragma unroll
            for (int r = 0; r < 4; r++) c[i][j][r] = 0.f;

    {
        float4 a0 = *(const float4*)Aptr0;
        float4 a1 = *(const float4*)Aptr1;
        float4 b0 = *(const float4*)Bptr0;
        float4 b1 = *(const float4*)Bptr1;
        As[0][lr][lk+0]=f2tf32(a0.x); As[0][lr][lk+1]=f2tf32(a0.y); As[0][lr][lk+2]=f2tf32(a0.z); As[0][lr][lk+3]=f2tf32(a0.w);
        As[0][64+lr][lk+0]=f2tf32(a1.x); As[0][64+lr][lk+1]=f2tf32(a1.y); As[0][64+lr][lk+2]=f2tf32(a1.z); As[0][64+lr][lk+3]=f2tf32(a1.w);
        Bs[0][lr][lk+0]=f2tf32(b0.x); Bs[0][lr][lk+1]=f2tf32(b0.y); Bs[0][lr][lk+2]=f2tf32(b0.z); Bs[0][lr][lk+3]=f2tf32(b0.w);
        Bs[0][64+lr][lk+0]=f2tf32(b1.x); Bs[0][64+lr][lk+1]=f2tf32(b1.y); Bs[0][64+lr][lk+2]=f2tf32(b1.z); Bs[0][64+lr][lk+3]=f2tf32(b1.w);
    }
    __syncthreads();

    const int T = K / 16;
    float4 pa0, pa1, pb0, pb1;
    for (int tI = 0; tI < T; tI++) {
        const int buf = tI & 1;
        const bool more = (tI + 1 < T);
        if (more) {
            const int off = (tI + 1) * 16;
            pa0 = *(const float4*)(Aptr0 + off);
            pa1 = *(const float4*)(Aptr1 + off);
            pb0 = *(const float4*)(Bptr0 + off);
            pb1 = *(const float4*)(Bptr1 + off);
        }

        #pragma unroll
        for (int kb = 0; kb < 16; kb += 8) {
            uint32_t afr[4][4];
            #pragma unroll
            for (int i = 0; i < 4; i++) {
                int mrow = wm + i*16 + ar;
                afr[i][0] = As[buf][mrow    ][kb + ac];
                afr[i][1] = As[buf][mrow + 8][kb + ac];
                afr[i][2] = As[buf][mrow    ][kb + ac + 4];
                afr[i][3] = As[buf][mrow + 8][kb + ac + 4];
            }
            uint32_t bfr[4][2];
            #pragma unroll
            for (int j = 0; j < 4; j++) {
                int nrow = wn + j*8 + ar;
                bfr[j][0] = Bs[buf][nrow][kb + ac];
                bfr[j][1] = Bs[buf][nrow][kb + ac + 4];
            }
            #pragma unroll
            for (int i = 0; i < 4; i++)
                #pragma unroll
                for (int j = 0; j < 4; j++)
                    mma_tf32(c[i][j][0], c[i][j][1], c[i][j][2], c[i][j][3],
                             afr[i][0], afr[i][1], afr[i][2], afr[i][3],
                             bfr[j][0], bfr[j][1]);
        }

        if (more) {
            const int nb = buf ^ 1;
            __syncthreads();
            As[nb][lr][lk+0]=f2tf32(pa0.x); As[nb][lr][lk+1]=f2tf32(pa0.y); As[nb][lr][lk+2]=f2tf32(pa0.z); As[nb][lr][lk+3]=f2tf32(pa0.w);
            As[nb][64+lr][lk+0]=f2tf32(pa1.x); As[nb][64+lr][lk+1]=f2tf32(pa1.y); As[nb][64+lr][lk+2]=f2tf32(pa1.z); As[nb][64+lr][lk+3]=f2tf32(pa1.w);
            Bs[nb][lr][lk+0]=f2tf32(pb0.x); Bs[nb][lr][lk+1]=f2tf32(pb0.y); Bs[nb][lr][lk+2]=f2tf32(pb0.z); Bs[nb][lr][lk+3]=f2tf32(pb0.w);
            Bs[nb][64+lr][lk+0]=f2tf32(pb1.x); Bs[nb][64+lr][lk+1]=f2tf32(pb1.y); Bs[nb][64+lr][lk+2]=f2tf32(pb1.z); Bs[nb][64+lr][lk+3]=f2tf32(pb1.w);
            __syncthreads();
        }
    }

    #pragma unroll
    for (int i = 0; i < 4; i++) {
        int row0 = m0 + wm + i*16 + ar;
        #pragma unroll
        for (int j = 0; j < 4; j++) {
            int col = n0 + wn + j*8 + 2*ac;
            float bsum0 = bias1[col]   + (bias2 ? bias2[col]   : 0.f);
            float bsum1 = bias1[col+1] + (bias2 ? bias2[col+1] : 0.f);
            *(float2*)(C + (size_t)row0 * N + col)       = make_float2(c[i][j][0] + bsum0, c[i][j][1] + bsum1);
            *(float2*)(C + (size_t)(row0 + 8) * N + col) = make_float2(c[i][j][2] + bsum0, c[i][j][3] + bsum1);
        }
    }
}

// ---------------- fp32 SIMT classifier GEMM (unchanged) ----------------
__global__ __launch_bounds__(256) void sgemm_cls_kernel(
    const float* __restrict__ A, const float* __restrict__ Bw,
    const float* __restrict__ bias1,
    float* __restrict__ C, int M, int N, int K)
{
    const int BM = 128, BN = 128, BK = 16;
    __shared__ float As[2][BK][BM];
    __shared__ float Bs[2][BK][BN];

    const int tid = threadIdx.x;
    const int m0 = blockIdx.y * BM;
    const int n0 = blockIdx.x * BN;
    const int ty = tid >> 4;
    const int tx = tid & 15;

    const int lr = tid >> 2;
    const int lk = (tid & 3) * 4;
    const float* Aptr0 = A + (size_t)(m0 + lr)      * K + lk;
    const float* Aptr1 = A + (size_t)(m0 + 64 + lr) * K + lk;
    const int bn0 = n0 + lr, bn1 = n0 + 64 + lr;
    const float* Bptr0 = Bw + (size_t)bn0 * K + lk;
    const float* Bptr1 = Bw + (size_t)bn1 * K + lk;
    const bool b0ok = bn0 < N, b1ok = bn1 < N;

    float acc[8][8];
    #pragma unroll
    for (int i = 0; i < 8; i++)
        #pragma unroll
        for (int j = 0; j < 8; j++) acc[i][j] = 0.f;

    const float4 z4 = make_float4(0.f,0.f,0.f,0.f);
    float4 av0, av1, bv0, bv1;

    av0 = *(const float4*)Aptr0;
    av1 = *(const float4*)Aptr1;
    bv0 = b0ok ? *(const float4*)Bptr0 : z4;
    bv1 = b1ok ? *(const float4*)Bptr1 : z4;
    As[0][lk+0][lr] = av0.x; As[0][lk+1][lr] = av0.y; As[0][lk+2][lr] = av0.z; As[0][lk+3][lr] = av0.w;
    As[0][lk+0][64+lr] = av1.x; As[0][lk+1][64+lr] = av1.y; As[0][lk+2][64+lr] = av1.z; As[0][lk+3][64+lr] = av1.w;
    Bs[0][lk+0][lr] = bv0.x; Bs[0][lk+1][lr] = bv0.y; Bs[0][lk+2][lr] = bv0.z; Bs[0][lk+3][lr] = bv0.w;
    Bs[0][lk+0][64+lr] = bv1.x; Bs[0][lk+1][64+lr] = bv1.y; Bs[0][lk+2][64+lr] = bv1.z; Bs[0][lk+3][64+lr] = bv1.w;
    __syncthreads();

    const int T = K / BK;
    for (int tI = 0; tI < T; tI++) {
        const int buf = tI & 1;
        const bool more = (tI + 1 < T);
        if (more) {
            const int off = (tI + 1) * BK;
            av0 = *(const float4*)(Aptr0 + off);
            av1 = *(const float4*)(Aptr1 + off);
            bv0 = b0ok ? *(const float4*)(Bptr0 + off) : z4;
            bv1 = b1ok ? *(const float4*)(Bptr1 + off) : z4;
        }
        #pragma unroll
        for (int k = 0; k < BK; k++) {
            float4 a0 = *(const float4*)&As[buf][k][ty*8];
            float4 a1 = *(const float4*)&As[buf][k][ty*8+4];
            float4 b0 = *(const float4*)&Bs[buf][k][tx*8];
            float4 b1 = *(const float4*)&Bs[buf][k][tx*8+4];
            float ar[8] = {a0.x,a0.y,a0.z,a0.w,a1.x,a1.y,a1.z,a1.w};
            float br[8] = {b0.x,b0.y,b0.z,b0.w,b1.x,b1.y,b1.z,b1.w};
            #pragma unroll
            for (int i = 0; i < 8; i++)
                #pragma unroll
                for (int j = 0; j < 8; j++)
                    acc[i][j] = fmaf(ar[i], br[j], acc[i][j]);
        }
        if (more) {
            const int nb = buf ^ 1;
            __syncthreads();
            As[nb][lk+0][lr] = av0.x; As[nb][lk+1][lr] = av0.y; As[nb][lk+2][lr] = av0.z; As[nb][lk+3][lr] = av0.w;
            As[nb][lk+0][64+lr] = av1.x; As[nb][lk+1][64+lr] = av1.y; As[nb][lk+2][64+lr] = av1.z; As[nb][lk+3][64+lr] = av1.w;
            Bs[nb][lk+0][lr] = bv0.x; Bs[nb][lk+1][lr] = bv0.y; Bs[nb][lk+2][lr] = bv0.z; Bs[nb][lk+3][lr] = bv0.w;
            Bs[nb][lk+0][64+lr] = bv1.x; Bs[nb][lk+1][64+lr] = bv1.y; Bs[nb][lk+2][64+lr] = bv1.z; Bs[nb][lk+3][64+lr] = bv1.w;
            __syncthreads();
        }
    }

    #pragma unroll
    for (int i = 0; i < 8; i++) {
        int m = m0 + ty*8 + i;
        #pragma unroll
        for (int j = 0; j < 8; j++) {
            int n = n0 + tx*8 + j;
            if (n < N) C[(size_t)m * N + n] = acc[i][j] + bias1[n];
        }
    }
}

// ---------------- persistent BiLSTM recurrence: tf32 mma, direct-L2 B frags -----------
// 128 blocks = dir(2) x jslice(32, 8 j each) x bhalf(2, 32 b each); 256 threads (8 warps).
// Warp w: mw=w&1 (m-tile), nw2=(w>>1)&1 (16-batch group), kh=w>>2 (128-k half).
// Whh resident in regs. B-fragments loaded per-lane straight from hbuf (L2, __ldcg),
// fed to mma as raw fp32 bits (hw tf32 truncation). Masked pass-through uses exact hst.
// Barrier: 8 distributed 32B-spaced arrival words per group; relaxed-MLP poll + fence.
// SMEM floats: part 2*32*33=2112, xg 32*33=1056, hst 256, lens 32 = 3456
#define SMEM_RECUR (3456 * 4)

__global__ __launch_bounds__(256, 1) void recur_kernel(
    const float* __restrict__ xg_f, const float* __restrict__ xg_b,
    const float* __restrict__ Whh_f, const float* __restrict__ Whh_b,
    const int* __restrict__ lengths, float* __restrict__ out,
    float* __restrict__ hbuf, int* __restrict__ bar)
{
    extern __shared__ float smem[];
    float* part   = smem;                    // [2 kh][32 r][33]
    float* xg_sm  = smem + 2112;             // [32 b][33]
    float* hst    = smem + 3168;             // [8 jj][32 b]  (this block's fp32 h)
    int*   lens_sm= (int*)(smem + 3424);     // [32]

    const int tid  = threadIdx.x;
    const int lane = tid & 31;
    const int warp = tid >> 5;
    const int blk = blockIdx.x;
    const int dir    = blk >> 6;
    const int jslice = (blk >> 1) & 31;
    const int bh     = blk & 1;
    const int j0 = jslice * 8;
    const int b0 = bh * 32;
    const int grp = dir * 2 + bh;
    const int myw = jslice & (NBARW - 1);    // arrival word within group
    const float* Whh = dir ? Whh_b : Whh_f;
    const float* xg  = dir ? xg_b  : xg_f;

    // warp mma coordinates
    const int mw  = warp & 1;
    const int nw2 = (warp >> 1) & 1;
    const int kh  = warp >> 2;
    const int lg  = lane >> 2;
    const int lc  = lane & 3;
    const int bcol0 = 16*nw2 + lg;
    const int khbase = kh * 128;

    // one-time Whh A-fragment load (resident all steps)
    uint32_t wfrag[16][4];
    #pragma unroll
    for (int ka = 0; ka < 16; ka++) {
        #pragma unroll
        for (int i = 0; i < 4; i++) {
            int r   = 16*mw + lg + (i & 1) * 8;
            int col = khbase + ka*8 + lc + (i >> 1) * 4;
            int g = r >> 3, jj = r & 7;
            wfrag[ka][i] = f2tf32(Whh[(size_t)(g*HID + j0 + jj) * HID + col]);
        }
    }
    if (tid < 32) lens_sm[tid] = lengths[b0 + tid];
    hst[tid] = 0.f;                      // h(s=0) = 0 for this block's j-slice

    // xg staging mapping
    const int sb    = tid >> 3;
    const int sg    = (tid >> 1) & 3;
    const int shalf = tid & 1;
    const size_t xg_row_base = ((size_t)(b0 + sb) * SEQ);
    const int xg_col = sg*HID + j0 + shalf*4;

    // combine mapping
    const int rr = tid >> 5;
    const int cb = tid & 31;
    float c_reg = 0.f;

    __syncthreads();

    int t0 = dir ? (SEQ - 1) : 0;
    float4 xg_pf = __ldg((const float4*)(xg + (xg_row_base + t0) * G4 + xg_col));

    for (int s = 0; s < SEQ; s++) {
        const int t = dir ? (SEQ - 1 - s) : s;

        if (s > 0) {
            if (tid == 0) {
                const int* base = bar + ((s-1)*4 + grp) * (NBARW*8);
                int sum;
                do {
                    sum = 0;
                    #pragma unroll
                    for (int q = 0; q < NBARW; q++) sum += ld_relaxed(base + q*8);
                } while (sum < GRP_BLOCKS);
                fence_acq();
            }
            __syncthreads();
        }

        // stage xg to smem + prefetch next xg (combine needs xg_sm after next sync)
        {
            float* xd = xg_sm + sb*33 + sg*8 + shalf*4;
            xd[0] = xg_pf.x; xd[1] = xg_pf.y; xd[2] = xg_pf.z; xd[3] = xg_pf.w;

            if (s + 1 < SEQ) {
                int tn = dir ? (SEQ - 2 - s) : (s + 1);
                xg_pf = __ldg((const float4*)(xg + (xg_row_base + tn) * G4 + xg_col));
            }
        }

        // tensor-core gate GEMM: B-frags straight from hbuf (L2), raw bits as tf32
        {
            const float* hcur = hbuf + (size_t)((s & 1)*2 + dir) * HID * BATCH;
            const float* hb   = hcur + (khbase + lc) * BATCH + b0 + bcol0;

            float acc[2][4];
            #pragma unroll
            for (int na = 0; na < 2; na++)
                #pragma unroll
                for (int r = 0; r < 4; r++) acc[na][r] = 0.f;

            #pragma unroll
            for (int ka = 0; ka < 16; ka++) {
                #pragma unroll
                for (int na = 0; na < 2; na++) {
                    uint32_t bf0 = __float_as_uint(__ldcg(hb + ka*8*BATCH + na*8));
                    uint32_t bf1 = __float_as_uint(__ldcg(hb + ka*8*BATCH + 4*BATCH + na*8));
                    mma_tf32(acc[na][0], acc[na][1], acc[na][2], acc[na][3],
                             wfrag[ka][0], wfrag[ka][1], wfrag[ka][2], wfrag[ka][3],
                             bf0, bf1);
                }
            }

            float* pd = part + kh*1056;
            #pragma unroll
            for (int na = 0; na < 2; na++) {
                int col = 16*nw2 + na*8 + 2*lc;
                int row = 16*mw + lg;
                pd[row*33 + col]         = acc[na][0];
                pd[row*33 + col + 1]     = acc[na][1];
                pd[(row + 8)*33 + col]   = acc[na][2];
                pd[(row + 8)*33 + col+1] = acc[na][3];
            }
        }
        __syncthreads();

        // combine: thread = (jj=rr, b=cb); h_prev from our own previous hst (fp32-exact)
        {
            float gate[4];
            #pragma unroll
            for (int g = 0; g < 4; g++) {
                int r = g*8 + rr;
                gate[g] = part[r*33 + cb] + part[1056 + r*33 + cb]
                        + xg_sm[cb*33 + g*8 + rr];
            }
            float h_prev = hst[rr*32 + cb];
            float c_new = sigf(gate[1]) * c_reg + sigf(gate[0]) * tanhf_(gate[2]);
            float h_new = sigf(gate[3]) * tanhf_(c_new);
            bool  m = (t < lens_sm[cb]);
            float h_out = m ? h_new : h_prev;
            c_reg       = m ? c_new : c_reg;

            hbuf[(size_t)(((s+1) & 1)*2 + dir) * HID * BATCH + (j0 + rr)*BATCH + b0 + cb] = h_out;
            hst[rr*32 + cb] = h_out;
        }
        __syncthreads();
        if (tid == 0) red_release_add(bar + ((s*4 + grp)*NBARW + myw)*8, 1);

        // semi-coalesced out store (64 threads x float4)
        if (tid < 64) {
            int bb  = tid >> 1;
            int seg = tid & 1;
            float4 v;
            v.x = hst[(seg*4+0)*32 + bb];
            v.y = hst[(seg*4+1)*32 + bb];
            v.z = hst[(seg*4+2)*32 + bb];
            v.w = hst[(seg*4+3)*32 + bb];
            *(float4*)(out + ((size_t)(b0 + bb) * SEQ + t) * (2*HID) + dir*HID + j0 + seg*4) = v;
        }
    }
}

// ---------------- launch ----------------
extern "C" void kernel_launch(void* const* d_in, const int* in_sizes, int n_in,
                              void* d_out, int out_size)
{
    (void)in_sizes; (void)n_in; (void)out_size;
    const int*   words    = (const int*)  d_in[0];
    const int*   lengths  = (const int*)  d_in[1];
    const float* emb      = (const float*)d_in[2];
    const float* l1f_Wih  = (const float*)d_in[3];
    const float* l1f_Whh  = (const float*)d_in[4];
    const float* l1f_bih  = (const float*)d_in[5];
    const float* l1f_bhh  = (const float*)d_in[6];
    const float* l1b_Wih  = (const float*)d_in[7];
    const float* l1b_Whh  = (const float*)d_in[8];
    const float* l1b_bih  = (const float*)d_in[9];
    const float* l1b_bhh  = (const float*)d_in[10];
    const float* l2f_Wih  = (const float*)d_in[11];
    const float* l2f_Whh  = (const float*)d_in[12];
    const float* l2f_bih  = (const float*)d_in[13];
    const float* l2f_bhh  = (const float*)d_in[14];
    const float* l2b_Wih  = (const float*)d_in[15];
    const float* l2b_Whh  = (const float*)d_in[16];
    const float* l2b_bih  = (const float*)d_in[17];
    const float* l2b_bhh  = (const float*)d_in[18];
    const float* cls_W    = (const float*)d_in[19];
    const float* cls_b    = (const float*)d_in[20];
    float* out = (float*)d_out;

    float *px, *pxf, *pxb, *po1, *po2, *ph1, *ph2;
    int *pbar;
    cudaGetSymbolAddress((void**)&px,   g_x);
    cudaGetSymbolAddress((void**)&pxf,  g_xg_f);
    cudaGetSymbolAddress((void**)&pxb,  g_xg_b);
    cudaGetSymbolAddress((void**)&po1,  g_o1);
    cudaGetSymbolAddress((void**)&po2,  g_o2);
    cudaGetSymbolAddress((void**)&ph1,  g_h1);
    cudaGetSymbolAddress((void**)&ph2,  g_h2);
    cudaGetSymbolAddress((void**)&pbar, g_bar);

    cudaFuncSetAttribute(recur_kernel, cudaFuncAttributeMaxDynamicSharedMemorySize, SMEM_RECUR);

    // 1) init (h buffers + all barrier words)
    init_kernel<<<1024, 256>>>();

    // 2) embedding
    embed_kernel<<<M_ROWS/8, 256>>>(words, emb);

    // 3) layer-1 input projections
    dim3 gx(G4/128, M_ROWS/128, 2);
    gemm_tf32_dual<<<gx, 256>>>(px, l1f_Wih, l1b_Wih,
                                l1f_bih, l1f_bhh, l1b_bih, l1b_bhh,
                                pxf, pxb, M_ROWS, G4, EMB);

    // 4) layer-1 recurrence
    recur_kernel<<<REC_BLOCKS, 256, SMEM_RECUR>>>(pxf, pxb, l1f_Whh, l1b_Whh,
                                                  lengths, po1, ph1, pbar);

    // 5) layer-2 input projections
    gemm_tf32_dual<<<gx, 256>>>(po1, l2f_Wih, l2b_Wih,
                                l2f_bih, l2f_bhh, l2b_bih, l2b_bhh,
                                pxf, pxb, M_ROWS, G4, 2*HID);

    // 6) layer-2 recurrence
    recur_kernel<<<REC_BLOCKS, 256, SMEM_RECUR>>>(pxf, pxb, l2f_Whh, l2b_Whh,
                                                  lengths, po2, ph2, pbar + SEQ*4*NBARW*8);

    // 7) classifier (fp32)
    dim3 gc(1, M_ROWS/128, 1);
    sgemm_cls_kernel<<<gc, 256>>>(po2, cls_W, cls_b, out, M_ROWS, NTAGS, 2*HID);
}

// round 11
// speedup vs baseline: 1.2265x; 1.2265x over previous
#include <cuda_runtime.h>
#include <cstdint>

#define BATCH 64
#define SEQ   512
#define EMB   128
#define HID   256
#define G4    1024            // 4*HID
#define NTAGS 50
#define M_ROWS (BATCH*SEQ)    // 32768
#define REC_BLOCKS 128        // 2 dirs * 32 j-slices * 2 batch-halves
#define GRP_BLOCKS 32         // blocks per (dir, bhalf) barrier group
#define NBARW 8               // distributed arrival words per group (32B apart)
#define HSTRIDE 40            // smem row stride (floats) for conflict-free B frags

// ---------------- scratch (device globals; allocation-free) ----------------
__device__ float g_x   [(size_t)M_ROWS*EMB];
__device__ float g_xg_f[(size_t)M_ROWS*G4];
__device__ float g_xg_b[(size_t)M_ROWS*G4];
__device__ float g_o1  [(size_t)M_ROWS*2*HID];
__device__ float g_o2  [(size_t)M_ROWS*2*HID];
__device__ float g_h1  [2][2][HID][BATCH];        // [parity][dir][k][b]
__device__ float g_h2  [2][2][HID][BATCH];
__device__ int   g_bar [2][SEQ][4][NBARW][8];     // [layer][step][group][word][pad 32B]

// ---------------- helpers ----------------
__device__ __forceinline__ int ld_relaxed(const int* p) {
    int v;
    asm volatile("ld.relaxed.gpu.global.b32 %0, [%1];" : "=r"(v) : "l"(p));
    return v;
}
__device__ __forceinline__ void fence_acq() {
    asm volatile("fence.acq_rel.gpu;" ::: "memory");
}
__device__ __forceinline__ void red_release_add(int* p, int v) {
    asm volatile("red.release.gpu.global.add.u32 [%0], %1;" :: "l"(p), "r"(v) : "memory");
}
__device__ __forceinline__ float sigf(float x)  { return 1.f/(1.f + __expf(-x)); }
__device__ __forceinline__ float tanhf_(float x){ return 1.f - 2.f/(__expf(2.f*x) + 1.f); }
__device__ __forceinline__ uint32_t f2tf32(float f) {
    uint32_t u;
    asm("cvt.rna.tf32.f32 %0, %1;" : "=r"(u) : "f"(f));
    return u;
}
__device__ __forceinline__ void mma_tf32(float& c0, float& c1, float& c2, float& c3,
                                         uint32_t a0, uint32_t a1, uint32_t a2, uint32_t a3,
                                         uint32_t b0, uint32_t b1) {
    asm volatile("mma.sync.aligned.m16n8k8.row.col.f32.tf32.tf32.f32 "
                 "{%0,%1,%2,%3}, {%4,%5,%6,%7}, {%8,%9}, {%0,%1,%2,%3};"
                 : "+f"(c0), "+f"(c1), "+f"(c2), "+f"(c3)
                 : "r"(a0), "r"(a1), "r"(a2), "r"(a3), "r"(b0), "r"(b1));
}

// ---------------- init ----------------
__global__ void init_kernel() {
    int i = blockIdx.x * blockDim.x + threadIdx.x;
    if (i < 2*2*HID*BATCH) {
        (&g_h1[0][0][0][0])[i] = 0.f;
        (&g_h2[0][0][0][0])[i] = 0.f;
    }
    if (i < 2*SEQ*4*NBARW*8) (&g_bar[0][0][0][0][0])[i] = 0;
}

// ---------------- embedding ----------------
__global__ void embed_kernel(const int* __restrict__ words, const float* __restrict__ emb) {
    int row = blockIdx.x * 8 + (threadIdx.x >> 5);
    int lane = threadIdx.x & 31;
    int w = words[row];
    const float4* src = (const float4*)(emb + (size_t)w * EMB);
    float4*       dst = (float4*)(g_x + (size_t)row * EMB);
    dst[lane] = src[lane];
}

// ---------------- tf32 tensor-core dual GEMM (unchanged) ----------------
__global__ __launch_bounds__(256) void gemm_tf32_dual(
    const float* __restrict__ A,
    const float* __restrict__ Bw_f, const float* __restrict__ Bw_b,
    const float* __restrict__ b1f, const float* __restrict__ b2f,
    const float* __restrict__ b1b, const float* __restrict__ b2b,
    float* __restrict__ Cf, float* __restrict__ Cb,
    int M, int N, int K)
{
    const float* Bw    = blockIdx.z ? Bw_b : Bw_f;
    const float* bias1 = blockIdx.z ? b1b  : b1f;
    const float* bias2 = blockIdx.z ? b2b  : b2f;
    float*       C     = blockIdx.z ? Cb   : Cf;

    __shared__ uint32_t As[2][128][20];
    __shared__ uint32_t Bs[2][128][20];

    const int tid  = threadIdx.x;
    const int lane = tid & 31;
    const int warp = tid >> 5;
    const int m0 = blockIdx.y * 128;
    const int n0 = blockIdx.x * 128;
    const int wm = (warp >> 2) * 64;
    const int wn = (warp & 3) * 32;
    const int ar = lane >> 2;
    const int ac = lane & 3;

    const int lr = tid >> 2;
    const int lk = (tid & 3) * 4;
    const float* Aptr0 = A  + (size_t)(m0 + lr)      * K + lk;
    const float* Aptr1 = A  + (size_t)(m0 + 64 + lr) * K + lk;
    const float* Bptr0 = Bw + (size_t)(n0 + lr)      * K + lk;
    const float* Bptr1 = Bw + (size_t)(n0 + 64 + lr) * K + lk;

    float c[4][4][4];
    #pragma unroll
    for (int i = 0; i < 4; i++)
        #pragma unroll
        for (int j = 0; j < 4; j++)
            #pragma unroll
            for (int r = 0; r < 4; r++) c[i][j][r] = 0.f;

    {
        float4 a0 = *(const float4*)Aptr0;
        float4 a1 = *(const float4*)Aptr1;
        float4 b0 = *(const float4*)Bptr0;
        float4 b1 = *(const float4*)Bptr1;
        As[0][lr][lk+0]=f2tf32(a0.x); As[0][lr][lk+1]=f2tf32(a0.y); As[0][lr][lk+2]=f2tf32(a0.z); As[0][lr][lk+3]=f2tf32(a0.w);
        As[0][64+lr][lk+0]=f2tf32(a1.x); As[0][64+lr][lk+1]=f2tf32(a1.y); As[0][64+lr][lk+2]=f2tf32(a1.z); As[0][64+lr][lk+3]=f2tf32(a1.w);
        Bs[0][lr][lk+0]=f2tf32(b0.x); Bs[0][lr][lk+1]=f2tf32(b0.y); Bs[0][lr][lk+2]=f2tf32(b0.z); Bs[0][lr][lk+3]=f2tf32(b0.w);
        Bs[0][64+lr][lk+0]=f2tf32(b1.x); Bs[0][64+lr][lk+1]=f2tf32(b1.y); Bs[0][64+lr][lk+2]=f2tf32(b1.z); Bs[0][64+lr][lk+3]=f2tf32(b1.w);
    }
    __syncthreads();

    const int T = K / 16;
    float4 pa0, pa1, pb0, pb1;
    for (int tI = 0; tI < T; tI++) {
        const int buf = tI & 1;
        const bool more = (tI + 1 < T);
        if (more) {
            const int off = (tI + 1) * 16;
            pa0 = *(const float4*)(Aptr0 + off);
            pa1 = *(const float4*)(Aptr1 + off);
            pb0 = *(const float4*)(Bptr0 + off);
            pb1 = *(const float4*)(Bptr1 + off);
        }

        #pragma unroll
        for (int kb = 0; kb < 16; kb += 8) {
            uint32_t afr[4][4];
            #pragma unroll
            for (int i = 0; i < 4; i++) {
                int mrow = wm + i*16 + ar;
                afr[i][0] = As[buf][mrow    ][kb + ac];
                afr[i][1] = As[buf][mrow + 8][kb + ac];
                afr[i][2] = As[buf][mrow    ][kb + ac + 4];
                afr[i][3] = As[buf][mrow + 8][kb + ac + 4];
            }
            uint32_t bfr[4][2];
            #pragma unroll
            for (int j = 0; j < 4; j++) {
                int nrow = wn + j*8 + ar;
                bfr[j][0] = Bs[buf][nrow][kb + ac];
                bfr[j][1] = Bs[buf][nrow][kb + ac + 4];
            }
            #pragma unroll
            for (int i = 0; i < 4; i++)
                #pragma unroll
                for (int j = 0; j < 4; j++)
                    mma_tf32(c[i][j][0], c[i][j][1], c[i][j][2], c[i][j][3],
                             afr[i][0], afr[i][1], afr[i][2], afr[i][3],
                             bfr[j][0], bfr[j][1]);
        }

        if (more) {
            const int nb = buf ^ 1;
            __syncthreads();
            As[nb][lr][lk+0]=f2tf32(pa0.x); As[nb][lr][lk+1]=f2tf32(pa0.y); As[nb][lr][lk+2]=f2tf32(pa0.z); As[nb][lr][lk+3]=f2tf32(pa0.w);
            As[nb][64+lr][lk+0]=f2tf32(pa1.x); As[nb][64+lr][lk+1]=f2tf32(pa1.y); As[nb][64+lr][lk+2]=f2tf32(pa1.z); As[nb][64+lr][lk+3]=f2tf32(pa1.w);
            Bs[nb][lr][lk+0]=f2tf32(pb0.x); Bs[nb][lr][lk+1]=f2tf32(pb0.y); Bs[nb][lr][lk+2]=f2tf32(pb0.z); Bs[nb][lr][lk+3]=f2tf32(pb0.w);
            Bs[nb][64+lr][lk+0]=f2tf32(pb1.x); Bs[nb][64+lr][lk+1]=f2tf32(pb1.y); Bs[nb][64+lr][lk+2]=f2tf32(pb1.z); Bs[nb][64+lr][lk+3]=f2tf32(pb1.w);
            __syncthreads();
        }
    }

    #pragma unroll
    for (int i = 0; i < 4; i++) {
        int row0 = m0 + wm + i*16 + ar;
        #pragma unroll
        for (int j = 0; j < 4; j++) {
            int col = n0 + wn + j*8 + 2*ac;
            float bsum0 = bias1[col]   + (bias2 ? bias2[col]   : 0.f);
            float bsum1 = bias1[col+1] + (bias2 ? bias2[col+1] : 0.f);
            *(float2*)(C + (size_t)row0 * N + col)       = make_float2(c[i][j][0] + bsum0, c[i][j][1] + bsum1);
            *(float2*)(C + (size_t)(row0 + 8) * N + col) = make_float2(c[i][j][2] + bsum0, c[i][j][3] + bsum1);
        }
    }
}

// ---------------- fp32 SIMT classifier GEMM (unchanged) ----------------
__global__ __launch_bounds__(256) void sgemm_cls_kernel(
    const float* __restrict__ A, const float* __restrict__ Bw,
    const float* __restrict__ bias1,
    float* __restrict__ C, int M, int N, int K)
{
    const int BM = 128, BN = 128, BK = 16;
    __shared__ float As[2][BK][BM];
    __shared__ float Bs[2][BK][BN];

    const int tid = threadIdx.x;
    const int m0 = blockIdx.y * BM;
    const int n0 = blockIdx.x * BN;
    const int ty = tid >> 4;
    const int tx = tid & 15;

    const int lr = tid >> 2;
    const int lk = (tid & 3) * 4;
    const float* Aptr0 = A + (size_t)(m0 + lr)      * K + lk;
    const float* Aptr1 = A + (size_t)(m0 + 64 + lr) * K + lk;
    const int bn0 = n0 + lr, bn1 = n0 + 64 + lr;
    const float* Bptr0 = Bw + (size_t)bn0 * K + lk;
    const float* Bptr1 = Bw + (size_t)bn1 * K + lk;
    const bool b0ok = bn0 < N, b1ok = bn1 < N;

    float acc[8][8];
    #pragma unroll
    for (int i = 0; i < 8; i++)
        #pragma unroll
        for (int j = 0; j < 8; j++) acc[i][j] = 0.f;

    const float4 z4 = make_float4(0.f,0.f,0.f,0.f);
    float4 av0, av1, bv0, bv1;

    av0 = *(const float4*)Aptr0;
    av1 = *(const float4*)Aptr1;
    bv0 = b0ok ? *(const float4*)Bptr0 : z4;
    bv1 = b1ok ? *(const float4*)Bptr1 : z4;
    As[0][lk+0][lr] = av0.x; As[0][lk+1][lr] = av0.y; As[0][lk+2][lr] = av0.z; As[0][lk+3][lr] = av0.w;
    As[0][lk+0][64+lr] = av1.x; As[0][lk+1][64+lr] = av1.y; As[0][lk+2][64+lr] = av1.z; As[0][lk+3][64+lr] = av1.w;
    Bs[0][lk+0][lr] = bv0.x; Bs[0][lk+1][lr] = bv0.y; Bs[0][lk+2][lr] = bv0.z; Bs[0][lk+3][lr] = bv0.w;
    Bs[0][lk+0][64+lr] = bv1.x; Bs[0][lk+1][64+lr] = bv1.y; Bs[0][lk+2][64+lr] = bv1.z; Bs[0][lk+3][64+lr] = bv1.w;
    __syncthreads();

    const int T = K / BK;
    for (int tI = 0; tI < T; tI++) {
        const int buf = tI & 1;
        const bool more = (tI + 1 < T);
        if (more) {
            const int off = (tI + 1) * BK;
            av0 = *(const float4*)(Aptr0 + off);
            av1 = *(const float4*)(Aptr1 + off);
            bv0 = b0ok ? *(const float4*)(Bptr0 + off) : z4;
            bv1 = b1ok ? *(const float4*)(Bptr1 + off) : z4;
        }
        #pragma unroll
        for (int k = 0; k < BK; k++) {
            float4 a0 = *(const float4*)&As[buf][k][ty*8];
            float4 a1 = *(const float4*)&As[buf][k][ty*8+4];
            float4 b0 = *(const float4*)&Bs[buf][k][tx*8];
            float4 b1 = *(const float4*)&Bs[buf][k][tx*8+4];
            float ar[8] = {a0.x,a0.y,a0.z,a0.w,a1.x,a1.y,a1.z,a1.w};
            float br[8] = {b0.x,b0.y,b0.z,b0.w,b1.x,b1.y,b1.z,b1.w};
            #pragma unroll
            for (int i = 0; i < 8; i++)
                #pragma unroll
                for (int j = 0; j < 8; j++)
                    acc[i][j] = fmaf(ar[i], br[j], acc[i][j]);
        }
        if (more) {
            const int nb = buf ^ 1;
            __syncthreads();
            As[nb][lk+0][lr] = av0.x; As[nb][lk+1][lr] = av0.y; As[nb][lk+2][lr] = av0.z; As[nb][lk+3][lr] = av0.w;
            As[nb][lk+0][64+lr] = av1.x; As[nb][lk+1][64+lr] = av1.y; As[nb][lk+2][64+lr] = av1.z; As[nb][lk+3][64+lr] = av1.w;
            Bs[nb][lk+0][lr] = bv0.x; Bs[nb][lk+1][lr] = bv0.y; Bs[nb][lk+2][lr] = bv0.z; Bs[nb][lk+3][lr] = bv0.w;
            Bs[nb][lk+0][64+lr] = bv1.x; Bs[nb][lk+1][64+lr] = bv1.y; Bs[nb][lk+2][64+lr] = bv1.z; Bs[nb][lk+3][64+lr] = bv1.w;
            __syncthreads();
        }
    }

    #pragma unroll
    for (int i = 0; i < 8; i++) {
        int m = m0 + ty*8 + i;
        #pragma unroll
        for (int j = 0; j < 8; j++) {
            int n = n0 + tx*8 + j;
            if (n < N) C[(size_t)m * N + n] = acc[i][j] + bias1[n];
        }
    }
}

// ---------------- persistent BiLSTM recurrence: tf32 mma, smem-staged h ----------------
// R9-proven structure + distributed barrier. 128 blocks = dir(2) x jslice(32) x bhalf(2).
// Warp w: mw=w&1 (m-tile), nw2=(w>>1)&1 (16-batch group), kh=w>>2 (128-k half).
// Whh resident in regs. h staged per step to smem as raw fp32 (mma truncates to tf32);
// masked pass-through uses the block's own exact hst.
// SMEM floats: ht 256*40=10240, part 2*32*33=2112, xg 32*33=1056, hst 256, lens 32 = 13696
#define SMEM_RECUR (13696 * 4)

__global__ __launch_bounds__(256, 1) void recur_kernel(
    const float* __restrict__ xg_f, const float* __restrict__ xg_b,
    const float* __restrict__ Whh_f, const float* __restrict__ Whh_b,
    const int* __restrict__ lengths, float* __restrict__ out,
    float* __restrict__ hbuf, int* __restrict__ bar)
{
    extern __shared__ float smem[];
    float* ht     = smem;                    // [256 k][40] raw fp32
    float* part   = smem + 10240;            // [2 kh][32 r][33]
    float* xg_sm  = smem + 12352;            // [32 b][33]
    float* hst    = smem + 13408;            // [8 jj][32 b]  (this block's fp32 h)
    int*   lens_sm= (int*)(smem + 13664);    // [32]

    const int tid  = threadIdx.x;
    const int lane = tid & 31;
    const int warp = tid >> 5;
    const int blk = blockIdx.x;
    const int dir    = blk >> 6;
    const int jslice = (blk >> 1) & 31;
    const int bh     = blk & 1;
    const int j0 = jslice * 8;
    const int b0 = bh * 32;
    const int grp = dir * 2 + bh;
    const int myw = jslice & (NBARW - 1);    // arrival word within group
    const float* Whh = dir ? Whh_b : Whh_f;
    const float* xg  = dir ? xg_b  : xg_f;

    // warp mma coordinates
    const int mw  = warp & 1;
    const int nw2 = (warp >> 1) & 1;
    const int kh  = warp >> 2;
    const int lg  = lane >> 2;
    const int lc  = lane & 3;
    const int bcol0 = 16*nw2 + lg;
    const int khbase = kh * 128;

    // one-time Whh A-fragment load (resident all steps)
    uint32_t wfrag[16][4];
    #pragma unroll
    for (int ka = 0; ka < 16; ka++) {
        #pragma unroll
        for (int i = 0; i < 4; i++) {
            int r   = 16*mw + lg + (i & 1) * 8;
            int col = khbase + ka*8 + lc + (i >> 1) * 4;
            int g = r >> 3, jj = r & 7;
            wfrag[ka][i] = f2tf32(Whh[(size_t)(g*HID + j0 + jj) * HID + col]);
        }
    }
    if (tid < 32) lens_sm[tid] = lengths[b0 + tid];
    hst[tid] = 0.f;                      // h(s=0) = 0

    // xg staging mapping
    const int sb    = tid >> 3;
    const int sg    = (tid >> 1) & 3;
    const int shalf = tid & 1;
    const size_t xg_row_base = ((size_t)(b0 + sb) * SEQ);
    const int xg_col = sg*HID + j0 + shalf*4;

    // combine mapping
    const int rr = tid >> 5;
    const int cb = tid & 31;
    float c_reg = 0.f;

    __syncthreads();

    int t0 = dir ? (SEQ - 1) : 0;
    float4 xg_pf = __ldg((const float4*)(xg + (xg_row_base + t0) * G4 + xg_col));

    for (int s = 0; s < SEQ; s++) {
        const int t = dir ? (SEQ - 1 - s) : s;

        if (s > 0) {
            if (tid == 0) {
                const int* base = bar + ((s-1)*4 + grp) * (NBARW*8);
                int sum;
                do {
                    sum = 0;
                    #pragma unroll
                    for (int q = 0; q < NBARW; q++) sum += ld_relaxed(base + q*8);
                } while (sum < GRP_BLOCKS);
                fence_acq();
            }
            __syncthreads();
        }

        // stage xg + h (raw fp32; mma truncates) + prefetch next xg
        {
            float* xd = xg_sm + sb*33 + sg*8 + shalf*4;
            xd[0] = xg_pf.x; xd[1] = xg_pf.y; xd[2] = xg_pf.z; xd[3] = xg_pf.w;

            const float* hsrc = hbuf + (size_t)((s & 1)*2 + dir) * HID * BATCH;
            #pragma unroll
            for (int n = 0; n < 8; n++) {
                int i = tid + n*256;                 // 0..2047
                int k = i >> 3, o = (i & 7)*4;
                float4 v = __ldcg((const float4*)(hsrc + k*BATCH + b0 + o));
                *(float4*)(ht + k*HSTRIDE + o) = v;
            }

            if (s + 1 < SEQ) {
                int tn = dir ? (SEQ - 2 - s) : (s + 1);
                xg_pf = __ldg((const float4*)(xg + (xg_row_base + tn) * G4 + xg_col));
            }
        }
        __syncthreads();

        // tensor-core gate GEMM over this warp's k-half (B frags from smem)
        {
            float acc[2][4];
            #pragma unroll
            for (int na = 0; na < 2; na++)
                #pragma unroll
                for (int r = 0; r < 4; r++) acc[na][r] = 0.f;

            #pragma unroll
            for (int ka = 0; ka < 16; ka++) {
                const float* hp = ht + (khbase + ka*8 + lc)*HSTRIDE;
                #pragma unroll
                for (int na = 0; na < 2; na++) {
                    const int bc = bcol0 + na*8;
                    uint32_t bf0 = __float_as_uint(hp[bc]);
                    uint32_t bf1 = __float_as_uint(hp[4*HSTRIDE + bc]);
                    mma_tf32(acc[na][0], acc[na][1], acc[na][2], acc[na][3],
                             wfrag[ka][0], wfrag[ka][1], wfrag[ka][2], wfrag[ka][3],
                             bf0, bf1);
                }
            }

            float* pd = part + kh*1056;
            #pragma unroll
            for (int na = 0; na < 2; na++) {
                int col = 16*nw2 + na*8 + 2*lc;
                int row = 16*mw + lg;
                pd[row*33 + col]         = acc[na][0];
                pd[row*33 + col + 1]     = acc[na][1];
                pd[(row + 8)*33 + col]   = acc[na][2];
                pd[(row + 8)*33 + col+1] = acc[na][3];
            }
        }
        __syncthreads();

        // combine: thread = (jj=rr, b=cb); h_prev from our own previous hst (fp32-exact)
        {
            float gate[4];
            #pragma unroll
            for (int g = 0; g < 4; g++) {
                int r = g*8 + rr;
                gate[g] = part[r*33 + cb] + part[1056 + r*33 + cb]
                        + xg_sm[cb*33 + g*8 + rr];
            }
            float h_prev = hst[rr*32 + cb];
            float c_new = sigf(gate[1]) * c_reg + sigf(gate[0]) * tanhf_(gate[2]);
            float h_new = sigf(gate[3]) * tanhf_(c_new);
            bool  m = (t < lens_sm[cb]);
            float h_out = m ? h_new : h_prev;
            c_reg       = m ? c_new : c_reg;

            hbuf[(size_t)(((s+1) & 1)*2 + dir) * HID * BATCH + (j0 + rr)*BATCH + b0 + cb] = h_out;
            hst[rr*32 + cb] = h_out;
        }
        __syncthreads();
        if (tid == 0) red_release_add(bar + ((s*4 + grp)*NBARW + myw)*8, 1);

        // semi-coalesced out store (64 threads x float4)
        if (tid < 64) {
            int bb  = tid >> 1;
            int seg = tid & 1;
            float4 v;
            v.x = hst[(seg*4+0)*32 + bb];
            v.y = hst[(seg*4+1)*32 + bb];
            v.z = hst[(seg*4+2)*32 + bb];
            v.w = hst[(seg*4+3)*32 + bb];
            *(float4*)(out + ((size_t)(b0 + bb) * SEQ + t) * (2*HID) + dir*HID + j0 + seg*4) = v;
        }
    }
}

// ---------------- launch ----------------
extern "C" void kernel_launch(void* const* d_in, const int* in_sizes, int n_in,
                              void* d_out, int out_size)
{
    (void)in_sizes; (void)n_in; (void)out_size;
    const int*   words    = (const int*)  d_in[0];
    const int*   lengths  = (const int*)  d_in[1];
    const float* emb      = (const float*)d_in[2];
    const float* l1f_Wih  = (const float*)d_in[3];
    const float* l1f_Whh  = (const float*)d_in[4];
    const float* l1f_bih  = (const float*)d_in[5];
    const float* l1f_bhh  = (const float*)d_in[6];
    const float* l1b_Wih  = (const float*)d_in[7];
    const float* l1b_Whh  = (const float*)d_in[8];
    const float* l1b_bih  = (const float*)d_in[9];
    const float* l1b_bhh  = (const float*)d_in[10];
    const float* l2f_Wih  = (const float*)d_in[11];
    const float* l2f_Whh  = (const float*)d_in[12];
    const float* l2f_bih  = (const float*)d_in[13];
    const float* l2f_bhh  = (const float*)d_in[14];
    const float* l2b_Wih  = (const float*)d_in[15];
    const float* l2b_Whh  = (const float*)d_in[16];
    const float* l2b_bih  = (const float*)d_in[17];
    const float* l2b_bhh  = (const float*)d_in[18];
    const float* cls_W    = (const float*)d_in[19];
    const float* cls_b    = (const float*)d_in[20];
    float* out = (float*)d_out;

    float *px, *pxf, *pxb, *po1, *po2, *ph1, *ph2;
    int *pbar;
    cudaGetSymbolAddress((void**)&px,   g_x);
    cudaGetSymbolAddress((void**)&pxf,  g_xg_f);
    cudaGetSymbolAddress((void**)&pxb,  g_xg_b);
    cudaGetSymbolAddress((void**)&po1,  g_o1);
    cudaGetSymbolAddress((void**)&po2,  g_o2);
    cudaGetSymbolAddress((void**)&ph1,  g_h1);
    cudaGetSymbolAddress((void**)&ph2,  g_h2);
    cudaGetSymbolAddress((void**)&pbar, g_bar);

    cudaFuncSetAttribute(recur_kernel, cudaFuncAttributeMaxDynamicSharedMemorySize, SMEM_RECUR);

    // 1) init (h buffers + all barrier words)
    init_kernel<<<1024, 256>>>();

    // 2) embedding
    embed_kernel<<<M_ROWS/8, 256>>>(words, emb);

    // 3) layer-1 input projections
    dim3 gx(G4/128, M_ROWS/128, 2);
    gemm_tf32_dual<<<gx, 256>>>(px, l1f_Wih, l1b_Wih,
                                l1f_bih, l1f_bhh, l1b_bih, l1b_bhh,
                                pxf, pxb, M_ROWS, G4, EMB);

    // 4) layer-1 recurrence
    recur_kernel<<<REC_BLOCKS, 256, SMEM_RECUR>>>(pxf, pxb, l1f_Whh, l1b_Whh,
                                                  lengths, po1, ph1, pbar);

    // 5) layer-2 input projections
    gemm_tf32_dual<<<gx, 256>>>(po1, l2f_Wih, l2b_Wih,
                                l2f_bih, l2f_bhh, l2b_bih, l2b_bhh,
                                pxf, pxb, M_ROWS, G4, 2*HID);

    // 6) layer-2 recurrence
    recur_kernel<<<REC_BLOCKS, 256, SMEM_RECUR>>>(pxf, pxb, l2f_Whh, l2b_Whh,
                                                  lengths, po2, ph2, pbar + SEQ*4*NBARW*8);

    // 7) classifier (fp32)
    dim3 gc(1, M_ROWS/128, 1);
    sgemm_cls_kernel<<<gc, 256>>>(po2, cls_W, cls_b, out, M_ROWS, NTAGS, 2*HID);
}

// round 12
// speedup vs baseline: 1.2632x; 1.0299x over previous
#include <cuda_runtime.h>
#include <cstdint>

#define BATCH 64
#define SEQ   512
#define EMB   128
#define HID   256
#define G4    1024            // 4*HID
#define NTAGS 50
#define M_ROWS (BATCH*SEQ)    // 32768
#define REC_BLOCKS 128        // 2 dirs * 32 j-slices * 2 batch-halves
#define HGRP 16               // producers per (group, j-half)
#define HSTRIDE 40            // smem row stride (floats) for conflict-free B frags

// ---------------- scratch (device globals; allocation-free) ----------------
__device__ float g_x   [(size_t)M_ROWS*EMB];
__device__ float g_xg_f[(size_t)M_ROWS*G4];
__device__ float g_xg_b[(size_t)M_ROWS*G4];
__device__ float g_o1  [(size_t)M_ROWS*2*HID];
__device__ float g_o2  [(size_t)M_ROWS*2*HID];
__device__ float g_h1  [2][2][HID][BATCH];        // [parity][dir][k][b]
__device__ float g_h2  [2][2][HID][BATCH];
__device__ int   g_bar [2][SEQ][4][2][8];         // [layer][step][group][jhalf][pad 32B]

// ---------------- helpers ----------------
__device__ __forceinline__ int ld_acquire(const int* p) {
    int v;
    asm volatile("ld.global.acquire.gpu.b32 %0, [%1];" : "=r"(v) : "l"(p));
    return v;
}
__device__ __forceinline__ void red_release_add(int* p, int v) {
    asm volatile("red.release.gpu.global.add.u32 [%0], %1;" :: "l"(p), "r"(v) : "memory");
}
__device__ __forceinline__ float sigf(float x)  { return 1.f/(1.f + __expf(-x)); }
__device__ __forceinline__ float tanhf_(float x){ return 1.f - 2.f/(__expf(2.f*x) + 1.f); }
__device__ __forceinline__ uint32_t f2tf32(float f) {
    uint32_t u;
    asm("cvt.rna.tf32.f32 %0, %1;" : "=r"(u) : "f"(f));
    return u;
}
__device__ __forceinline__ void mma_tf32(float& c0, float& c1, float& c2, float& c3,
                                         uint32_t a0, uint32_t a1, uint32_t a2, uint32_t a3,
                                         uint32_t b0, uint32_t b1) {
    asm volatile("mma.sync.aligned.m16n8k8.row.col.f32.tf32.tf32.f32 "
                 "{%0,%1,%2,%3}, {%4,%5,%6,%7}, {%8,%9}, {%0,%1,%2,%3};"
                 : "+f"(c0), "+f"(c1), "+f"(c2), "+f"(c3)
                 : "r"(a0), "r"(a1), "r"(a2), "r"(a3), "r"(b0), "r"(b1));
}

// ---------------- init ----------------
__global__ void init_kernel() {
    int i = blockIdx.x * blockDim.x + threadIdx.x;
    if (i < 2*2*HID*BATCH) {
        (&g_h1[0][0][0][0])[i] = 0.f;
        (&g_h2[0][0][0][0])[i] = 0.f;
    }
    if (i < 2*SEQ*4*2*8) (&g_bar[0][0][0][0][0])[i] = 0;
}

// ---------------- embedding ----------------
__global__ void embed_kernel(const int* __restrict__ words, const float* __restrict__ emb) {
    int row = blockIdx.x * 8 + (threadIdx.x >> 5);
    int lane = threadIdx.x & 31;
    int w = words[row];
    const float4* src = (const float4*)(emb + (size_t)w * EMB);
    float4*       dst = (float4*)(g_x + (size_t)row * EMB);
    dst[lane] = src[lane];
}

// ---------------- tf32 tensor-core dual GEMM (unchanged) ----------------
__global__ __launch_bounds__(256) void gemm_tf32_dual(
    const float* __restrict__ A,
    const float* __restrict__ Bw_f, const float* __restrict__ Bw_b,
    const float* __restrict__ b1f, const float* __restrict__ b2f,
    const float* __restrict__ b1b, const float* __restrict__ b2b,
    float* __restrict__ Cf, float* __restrict__ Cb,
    int M, int N, int K)
{
    const float* Bw    = blockIdx.z ? Bw_b : Bw_f;
    const float* bias1 = blockIdx.z ? b1b  : b1f;
    const float* bias2 = blockIdx.z ? b2b  : b2f;
    float*       C     = blockIdx.z ? Cb   : Cf;

    __shared__ uint32_t As[2][128][20];
    __shared__ uint32_t Bs[2][128][20];

    const int tid  = threadIdx.x;
    const int lane = tid & 31;
    const int warp = tid >> 5;
    const int m0 = blockIdx.y * 128;
    const int n0 = blockIdx.x * 128;
    const int wm = (warp >> 2) * 64;
    const int wn = (warp & 3) * 32;
    const int ar = lane >> 2;
    const int ac = lane & 3;

    const int lr = tid >> 2;
    const int lk = (tid & 3) * 4;
    const float* Aptr0 = A  + (size_t)(m0 + lr)      * K + lk;
    const float* Aptr1 = A  + (size_t)(m0 + 64 + lr) * K + lk;
    const float* Bptr0 = Bw + (size_t)(n0 + lr)      * K + lk;
    const float* Bptr1 = Bw + (size_t)(n0 + 64 + lr) * K + lk;

    float c[4][4][4];
    #pragma unroll
    for (int i = 0; i < 4; i++)
        #pragma unroll
        for (int j = 0; j < 4; j++)
            #pragma unroll
            for (int r = 0; r < 4; r++) c[i][j][r] = 0.f;

    {
        float4 a0 = *(const float4*)Aptr0;
        float4 a1 = *(const float4*)Aptr1;
        float4 b0 = *(const float4*)Bptr0;
        float4 b1 = *(const float4*)Bptr1;
        As[0][lr][lk+0]=f2tf32(a0.x); As[0][lr][lk+1]=f2tf32(a0.y); As[0][lr][lk+2]=f2tf32(a0.z); As[0][lr][lk+3]=f2tf32(a0.w);
        As[0][64+lr][lk+0]=f2tf32(a1.x); As[0][64+lr][lk+1]=f2tf32(a1.y); As[0][64+lr][lk+2]=f2tf32(a1.z); As[0][64+lr][lk+3]=f2tf32(a1.w);
        Bs[0][lr][lk+0]=f2tf32(b0.x); Bs[0][lr][lk+1]=f2tf32(b0.y); Bs[0][lr][lk+2]=f2tf32(b0.z); Bs[0][lr][lk+3]=f2tf32(b0.w);
        Bs[0][64+lr][lk+0]=f2tf32(b1.x); Bs[0][64+lr][lk+1]=f2tf32(b1.y); Bs[0][64+lr][lk+2]=f2tf32(b1.z); Bs[0][64+lr][lk+3]=f2tf32(b1.w);
    }
    __syncthreads();

    const int T = K / 16;
    float4 pa0, pa1, pb0, pb1;
    for (int tI = 0; tI < T; tI++) {
        const int buf = tI & 1;
        const bool more = (tI + 1 < T);
        if (more) {
            const int off = (tI + 1) * 16;
            pa0 = *(const float4*)(Aptr0 + off);
            pa1 = *(const float4*)(Aptr1 + off);
            pb0 = *(const float4*)(Bptr0 + off);
            pb1 = *(const float4*)(Bptr1 + off);
        }

        #pragma unroll
        for (int kb = 0; kb < 16; kb += 8) {
            uint32_t afr[4][4];
            #pragma unroll
            for (int i = 0; i < 4; i++) {
                int mrow = wm + i*16 + ar;
                afr[i][0] = As[buf][mrow    ][kb + ac];
                afr[i][1] = As[buf][mrow + 8][kb + ac];
                afr[i][2] = As[buf][mrow    ][kb + ac + 4];
                afr[i][3] = As[buf][mrow + 8][kb + ac + 4];
            }
            uint32_t bfr[4][2];
            #pragma unroll
            for (int j = 0; j < 4; j++) {
                int nrow = wn + j*8 + ar;
                bfr[j][0] = Bs[buf][nrow][kb + ac];
                bfr[j][1] = Bs[buf][nrow][kb + ac + 4];
            }
            #pragma unroll
            for (int i = 0; i < 4; i++)
                #pragma unroll
                for (int j = 0; j < 4; j++)
                    mma_tf32(c[i][j][0], c[i][j][1], c[i][j][2], c[i][j][3],
                             afr[i][0], afr[i][1], afr[i][2], afr[i][3],
                             bfr[j][0], bfr[j][1]);
        }

        if (more) {
            const int nb = buf ^ 1;
            __syncthreads();
            As[nb][lr][lk+0]=f2tf32(pa0.x); As[nb][lr][lk+1]=f2tf32(pa0.y); As[nb][lr][lk+2]=f2tf32(pa0.z); As[nb][lr][lk+3]=f2tf32(pa0.w);
            As[nb][64+lr][lk+0]=f2tf32(pa1.x); As[nb][64+lr][lk+1]=f2tf32(pa1.y); As[nb][64+lr][lk+2]=f2tf32(pa1.z); As[nb][64+lr][lk+3]=f2tf32(pa1.w);
            Bs[nb][lr][lk+0]=f2tf32(pb0.x); Bs[nb][lr][lk+1]=f2tf32(pb0.y); Bs[nb][lr][lk+2]=f2tf32(pb0.z); Bs[nb][lr][lk+3]=f2tf32(pb0.w);
            Bs[nb][64+lr][lk+0]=f2tf32(pb1.x); Bs[nb][64+lr][lk+1]=f2tf32(pb1.y); Bs[nb][64+lr][lk+2]=f2tf32(pb1.z); Bs[nb][64+lr][lk+3]=f2tf32(pb1.w);
            __syncthreads();
        }
    }

    #pragma unroll
    for (int i = 0; i < 4; i++) {
        int row0 = m0 + wm + i*16 + ar;
        #pragma unroll
        for (int j = 0; j < 4; j++) {
            int col = n0 + wn + j*8 + 2*ac;
            float bsum0 = bias1[col]   + (bias2 ? bias2[col]   : 0.f);
            float bsum1 = bias1[col+1] + (bias2 ? bias2[col+1] : 0.f);
            *(float2*)(C + (size_t)row0 * N + col)       = make_float2(c[i][j][0] + bsum0, c[i][j][1] + bsum1);
            *(float2*)(C + (size_t)(row0 + 8) * N + col) = make_float2(c[i][j][2] + bsum0, c[i][j][3] + bsum1);
        }
    }
}

// ---------------- fp32 SIMT classifier GEMM (unchanged) ----------------
__global__ __launch_bounds__(256) void sgemm_cls_kernel(
    const float* __restrict__ A, const float* __restrict__ Bw,
    const float* __restrict__ bias1,
    float* __restrict__ C, int M, int N, int K)
{
    const int BM = 128, BN = 128, BK = 16;
    __shared__ float As[2][BK][BM];
    __shared__ float Bs[2][BK][BN];

    const int tid = threadIdx.x;
    const int m0 = blockIdx.y * BM;
    const int n0 = blockIdx.x * BN;
    const int ty = tid >> 4;
    const int tx = tid & 15;

    const int lr = tid >> 2;
    const int lk = (tid & 3) * 4;
    const float* Aptr0 = A + (size_t)(m0 + lr)      * K + lk;
    const float* Aptr1 = A + (size_t)(m0 + 64 + lr) * K + lk;
    const int bn0 = n0 + lr, bn1 = n0 + 64 + lr;
    const float* Bptr0 = Bw + (size_t)bn0 * K + lk;
    const float* Bptr1 = Bw + (size_t)bn1 * K + lk;
    const bool b0ok = bn0 < N, b1ok = bn1 < N;

    float acc[8][8];
    #pragma unroll
    for (int i = 0; i < 8; i++)
        #pragma unroll
        for (int j = 0; j < 8; j++) acc[i][j] = 0.f;

    const float4 z4 = make_float4(0.f,0.f,0.f,0.f);
    float4 av0, av1, bv0, bv1;

    av0 = *(const float4*)Aptr0;
    av1 = *(const float4*)Aptr1;
    bv0 = b0ok ? *(const float4*)Bptr0 : z4;
    bv1 = b1ok ? *(const float4*)Bptr1 : z4;
    As[0][lk+0][lr] = av0.x; As[0][lk+1][lr] = av0.y; As[0][lk+2][lr] = av0.z; As[0][lk+3][lr] = av0.w;
    As[0][lk+0][64+lr] = av1.x; As[0][lk+1][64+lr] = av1.y; As[0][lk+2][64+lr] = av1.z; As[0][lk+3][64+lr] = av1.w;
    Bs[0][lk+0][lr] = bv0.x; Bs[0][lk+1][lr] = bv0.y; Bs[0][lk+2][lr] = bv0.z; Bs[0][lk+3][lr] = bv0.w;
    Bs[0][lk+0][64+lr] = bv1.x; Bs[0][lk+1][64+lr] = bv1.y; Bs[0][lk+2][64+lr] = bv1.z; Bs[0][lk+3][64+lr] = bv1.w;
    __syncthreads();

    const int T = K / BK;
    for (int tI = 0; tI < T; tI++) {
        const int buf = tI & 1;
        const bool more = (tI + 1 < T);
        if (more) {
            const int off = (tI + 1) * BK;
            av0 = *(const float4*)(Aptr0 + off);
            av1 = *(const float4*)(Aptr1 + off);
            bv0 = b0ok ? *(const float4*)(Bptr0 + off) : z4;
            bv1 = b1ok ? *(const float4*)(Bptr1 + off) : z4;
        }
        #pragma unroll
        for (int k = 0; k < BK; k++) {
            float4 a0 = *(const float4*)&As[buf][k][ty*8];
            float4 a1 = *(const float4*)&As[buf][k][ty*8+4];
            float4 b0 = *(const float4*)&Bs[buf][k][tx*8];
            float4 b1 = *(const float4*)&Bs[buf][k][tx*8+4];
            float ar[8] = {a0.x,a0.y,a0.z,a0.w,a1.x,a1.y,a1.z,a1.w};
            float br[8] = {b0.x,b0.y,b0.z,b0.w,b1.x,b1.y,b1.z,b1.w};
            #pragma unroll
            for (int i = 0; i < 8; i++)
                #pragma unroll
                for (int j = 0; j < 8; j++)
                    acc[i][j] = fmaf(ar[i], br[j], acc[i][j]);
        }
        if (more) {
            const int nb = buf ^ 1;
            __syncthreads();
            As[nb][lk+0][lr] = av0.x; As[nb][lk+1][lr] = av0.y; As[nb][lk+2][lr] = av0.z; As[nb][lk+3][lr] = av0.w;
            As[nb][lk+0][64+lr] = av1.x; As[nb][lk+1][64+lr] = av1.y; As[nb][lk+2][64+lr] = av1.z; As[nb][lk+3][64+lr] = av1.w;
            Bs[nb][lk+0][lr] = bv0.x; Bs[nb][lk+1][lr] = bv0.y; Bs[nb][lk+2][lr] = bv0.z; Bs[nb][lk+3][lr] = bv0.w;
            Bs[nb][lk+0][64+lr] = bv1.x; Bs[nb][lk+1][64+lr] = bv1.y; Bs[nb][lk+2][64+lr] = bv1.z; Bs[nb][lk+3][64+lr] = bv1.w;
            __syncthreads();
        }
    }

    #pragma unroll
    for (int i = 0; i < 8; i++) {
        int m = m0 + ty*8 + i;
        #pragma unroll
        for (int j = 0; j < 8; j++) {
            int n = n0 + tx*8 + j;
            if (n < N) C[(size_t)m * N + n] = acc[i][j] + bias1[n];
        }
    }
}

// ---------------- persistent BiLSTM recurrence: tf32 mma, j-half split barrier -----------
// 128 blocks = dir(2) x jslice(32, 8 j each) x bhalf(2, 32 b each); 256 threads (8 warps).
// Warp w: mw=w&1 (m-tile), nw2=(w>>1)&1 (16-batch group), kh=w>>2 (128-k half).
// Barrier: one acquire-word per (group, j-half); warps wait only on the half they consume
// (kh group), then stage that k-half cooperatively (named barrier) and run mma.
// SMEM floats: ht 256*40=10240, part 2*32*33=2112, xg 32*33=1056, hst 256, lens 32 = 13696
#define SMEM_RECUR (13696 * 4)

__global__ __launch_bounds__(256, 1) void recur_kernel(
    const float* __restrict__ xg_f, const float* __restrict__ xg_b,
    const float* __restrict__ Whh_f, const float* __restrict__ Whh_b,
    const int* __restrict__ lengths, float* __restrict__ out,
    float* __restrict__ hbuf, int* __restrict__ bar)
{
    extern __shared__ float smem[];
    float* ht     = smem;                    // [256 k][40] raw fp32
    float* part   = smem + 10240;            // [2 kh][32 r][33]
    float* xg_sm  = smem + 12352;            // [32 b][33]
    float* hst    = smem + 13408;            // [8 jj][32 b]  (this block's fp32 h)
    int*   lens_sm= (int*)(smem + 13664);    // [32]

    const int tid  = threadIdx.x;
    const int lane = tid & 31;
    const int warp = tid >> 5;
    const int blk = blockIdx.x;
    const int dir    = blk >> 6;
    const int jslice = (blk >> 1) & 31;
    const int bh     = blk & 1;
    const int j0 = jslice * 8;
    const int b0 = bh * 32;
    const int grp = dir * 2 + bh;
    const int myjh = jslice >> 4;            // this block's j-half (0: j<128, 1: j>=128)
    const float* Whh = dir ? Whh_b : Whh_f;
    const float* xg  = dir ? xg_b  : xg_f;

    // warp mma coordinates
    const int mw  = warp & 1;
    const int nw2 = (warp >> 1) & 1;
    const int kh  = warp >> 2;               // k-half this warp consumes
    const int lg  = lane >> 2;
    const int lc  = lane & 3;
    const int bcol0 = 16*nw2 + lg;
    const int khbase = kh * 128;
    const int wtid = tid & 127;              // thread id within kh group

    // one-time Whh A-fragment load (resident all steps)
    uint32_t wfrag[16][4];
    #pragma unroll
    for (int ka = 0; ka < 16; ka++) {
        #pragma unroll
        for (int i = 0; i < 4; i++) {
            int r   = 16*mw + lg + (i & 1) * 8;
            int col = khbase + ka*8 + lc + (i >> 1) * 4;
            int g = r >> 3, jj = r & 7;
            wfrag[ka][i] = f2tf32(Whh[(size_t)(g*HID + j0 + jj) * HID + col]);
        }
    }
    if (tid < 32) lens_sm[tid] = lengths[b0 + tid];
    hst[tid] = 0.f;                      // h(s=0) = 0

    // xg staging mapping
    const int sb    = tid >> 3;
    const int sg    = (tid >> 1) & 3;
    const int shalf = tid & 1;
    const size_t xg_row_base = ((size_t)(b0 + sb) * SEQ);
    const int xg_col = sg*HID + j0 + shalf*4;

    // combine mapping
    const int rr = tid >> 5;
    const int cb = tid & 31;
    float c_reg = 0.f;

    __syncthreads();

    int t0 = dir ? (SEQ - 1) : 0;
    float4 xg_pf = __ldg((const float4*)(xg + (xg_row_base + t0) * G4 + xg_col));

    for (int s = 0; s < SEQ; s++) {
        const int t = dir ? (SEQ - 1 - s) : s;

        // per-warp wait on the j-half this warp consumes
        if (s > 0) {
            if (lane == 0) {
                const int* cnt = bar + (((s-1)*4 + grp)*2 + kh)*8;
                while (ld_acquire(cnt) < HGRP) __nanosleep(40);
            }
            __syncwarp();
        }

        // stage xg (all threads) + this kh-group's h half (128 threads) + prefetch next xg
        {
            float* xd = xg_sm + sb*33 + sg*8 + shalf*4;
            xd[0] = xg_pf.x; xd[1] = xg_pf.y; xd[2] = xg_pf.z; xd[3] = xg_pf.w;

            const float* hsrc = hbuf + (size_t)((s & 1)*2 + dir) * HID * BATCH + (size_t)khbase * BATCH;
            #pragma unroll
            for (int n = 0; n < 8; n++) {
                int i = wtid + n*128;                // 0..1023 within half
                int k = i >> 3, o = (i & 7)*4;       // k local 0..127
                float4 v = __ldcg((const float4*)(hsrc + k*BATCH + b0 + o));
                *(float4*)(ht + (khbase + k)*HSTRIDE + o) = v;
            }

            if (s + 1 < SEQ) {
                int tn = dir ? (SEQ - 2 - s) : (s + 1);
                xg_pf = __ldg((const float4*)(xg + (xg_row_base + tn) * G4 + xg_col));
            }
        }
        // kh-group join: all 4 warps of this half finished staging
        asm volatile("bar.sync %0, 128;" :: "r"(kh + 1) : "memory");

        // tensor-core gate GEMM over this warp's k-half (B frags from smem)
        {
            float acc[2][4];
            #pragma unroll
            for (int na = 0; na < 2; na++)
                #pragma unroll
                for (int r = 0; r < 4; r++) acc[na][r] = 0.f;

            #pragma unroll
            for (int ka = 0; ka < 16; ka++) {
                const float* hp = ht + (khbase + ka*8 + lc)*HSTRIDE;
                #pragma unroll
                for (int na = 0; na < 2; na++) {
                    const int bc = bcol0 + na*8;
                    uint32_t bf0 = __float_as_uint(hp[bc]);
                    uint32_t bf1 = __float_as_uint(hp[4*HSTRIDE + bc]);
                    mma_tf32(acc[na][0], acc[na][1], acc[na][2], acc[na][3],
                             wfrag[ka][0], wfrag[ka][1], wfrag[ka][2], wfrag[ka][3],
                             bf0, bf1);
                }
            }

            float* pd = part + kh*1056;
            #pragma unroll
            for (int na = 0; na < 2; na++) {
                int col = 16*nw2 + na*8 + 2*lc;
                int row = 16*mw + lg;
                pd[row*33 + col]         = acc[na][0];
                pd[row*33 + col + 1]     = acc[na][1];
                pd[(row + 8)*33 + col]   = acc[na][2];
                pd[(row + 8)*33 + col+1] = acc[na][3];
            }
        }
        __syncthreads();

        // combine: thread = (jj=rr, b=cb); h_prev from our own previous hst (fp32-exact)
        {
            float gate[4];
            #pragma unroll
            for (int g = 0; g < 4; g++) {
                int r = g*8 + rr;
                gate[g] = part[r*33 + cb] + part[1056 + r*33 + cb]
                        + xg_sm[cb*33 + g*8 + rr];
            }
            float h_prev = hst[rr*32 + cb];
            float c_new = sigf(gate[1]) * c_reg + sigf(gate[0]) * tanhf_(gate[2]);
            float h_new = sigf(gate[3]) * tanhf_(c_new);
            bool  m = (t < lens_sm[cb]);
            float h_out = m ? h_new : h_prev;
            c_reg       = m ? c_new : c_reg;

            hbuf[(size_t)(((s+1) & 1)*2 + dir) * HID * BATCH + (j0 + rr)*BATCH + b0 + cb] = h_out;
            hst[rr*32 + cb] = h_out;
        }
        __syncthreads();
        if (tid == 0) red_release_add(bar + ((s*4 + grp)*2 + myjh)*8, 1);

        // semi-coalesced out store (64 threads x float4)
        if (tid < 64) {
            int bb  = tid >> 1;
            int seg = tid & 1;
            float4 v;
            v.x = hst[(seg*4+0)*32 + bb];
            v.y = hst[(seg*4+1)*32 + bb];
            v.z = hst[(seg*4+2)*32 + bb];
            v.w = hst[(seg*4+3)*32 + bb];
            *(float4*)(out + ((size_t)(b0 + bb) * SEQ + t) * (2*HID) + dir*HID + j0 + seg*4) = v;
        }
    }
}

// ---------------- launch ----------------
extern "C" void kernel_launch(void* const* d_in, const int* in_sizes, int n_in,
                              void* d_out, int out_size)
{
    (void)in_sizes; (void)n_in; (void)out_size;
    const int*   words    = (const int*)  d_in[0];
    const int*   lengths  = (const int*)  d_in[1];
    const float* emb      = (const float*)d_in[2];
    const float* l1f_Wih  = (const float*)d_in[3];
    const float* l1f_Whh  = (const float*)d_in[4];
    const float* l1f_bih  = (const float*)d_in[5];
    const float* l1f_bhh  = (const float*)d_in[6];
    const float* l1b_Wih  = (const float*)d_in[7];
    const float* l1b_Whh  = (const float*)d_in[8];
    const float* l1b_bih  = (const float*)d_in[9];
    const float* l1b_bhh  = (const float*)d_in[10];
    const float* l2f_Wih  = (const float*)d_in[11];
    const float* l2f_Whh  = (const float*)d_in[12];
    const float* l2f_bih  = (const float*)d_in[13];
    const float* l2f_bhh  = (const float*)d_in[14];
    const float* l2b_Wih  = (const float*)d_in[15];
    const float* l2b_Whh  = (const float*)d_in[16];
    const float* l2b_bih  = (const float*)d_in[17];
    const float* l2b_bhh  = (const float*)d_in[18];
    const float* cls_W    = (const float*)d_in[19];
    const float* cls_b    = (const float*)d_in[20];
    float* out = (float*)d_out;

    float *px, *pxf, *pxb, *po1, *po2, *ph1, *ph2;
    int *pbar;
    cudaGetSymbolAddress((void**)&px,   g_x);
    cudaGetSymbolAddress((void**)&pxf,  g_xg_f);
    cudaGetSymbolAddress((void**)&pxb,  g_xg_b);
    cudaGetSymbolAddress((void**)&po1,  g_o1);
    cudaGetSymbolAddress((void**)&po2,  g_o2);
    cudaGetSymbolAddress((void**)&ph1,  g_h1);
    cudaGetSymbolAddress((void**)&ph2,  g_h2);
    cudaGetSymbolAddress((void**)&pbar, g_bar);

    cudaFuncSetAttribute(recur_kernel, cudaFuncAttributeMaxDynamicSharedMemorySize, SMEM_RECUR);

    // 1) init (h buffers + all barrier words)
    init_kernel<<<256, 256>>>();

    // 2) embedding
    embed_kernel<<<M_ROWS/8, 256>>>(words, emb);

    // 3) layer-1 input projections
    dim3 gx(G4/128, M_ROWS/128, 2);
    gemm_tf32_dual<<<gx, 256>>>(px, l1f_Wih, l1b_Wih,
                                l1f_bih, l1f_bhh, l1b_bih, l1b_bhh,
                                pxf, pxb, M_ROWS, G4, EMB);

    // 4) layer-1 recurrence
    recur_kernel<<<REC_BLOCKS, 256, SMEM_RECUR>>>(pxf, pxb, l1f_Whh, l1b_Whh,
                                                  lengths, po1, ph1, pbar);

    // 5) layer-2 input projections
    gemm_tf32_dual<<<gx, 256>>>(po1, l2f_Wih, l2b_Wih,
                                l2f_bih, l2f_bhh, l2b_bih, l2b_bhh,
                                pxf, pxb, M_ROWS, G4, 2*HID);

    // 6) layer-2 recurrence
    recur_kernel<<<REC_BLOCKS, 256, SMEM_RECUR>>>(pxf, pxb, l2f_Whh, l2b_Whh,
                                                  lengths, po2, ph2, pbar + SEQ*4*2*8);

    // 7) classifier (fp32)
    dim3 gc(1, M_ROWS/128, 1);
    sgemm_cls_kernel<<<gc, 256>>>(po2, cls_W, cls_b, out, M_ROWS, NTAGS, 2*HID);
}

// round 13
// speedup vs baseline: 1.3968x; 1.1058x over previous
#include <cuda_runtime.h>
#include <cstdint>

#define BATCH 64
#define SEQ   512
#define EMB   128
#define HID   256
#define G4    1024            // 4*HID
#define NTAGS 50
#define M_ROWS (BATCH*SEQ)    // 32768
#define REC_BLOCKS 128        // 2 dirs * 32 j-slices * 2 batch-halves
#define GRP_BLOCKS 32         // blocks per (dir, bhalf) barrier group
#define HSTRIDE 40            // smem row stride (floats) for conflict-free B frags

// ---------------- scratch (device globals; allocation-free) ----------------
__device__ float g_x   [(size_t)M_ROWS*EMB];
__device__ float g_xg_f[(size_t)M_ROWS*G4];
__device__ float g_xg_b[(size_t)M_ROWS*G4];
__device__ float g_o1  [(size_t)M_ROWS*2*HID];
__device__ float g_o2  [(size_t)M_ROWS*2*HID];
__device__ float g_h1  [2][2][HID][BATCH];        // [parity][dir][k][b]
__device__ float g_h2  [2][2][HID][BATCH];
__device__ int   g_bar [2][SEQ][4][8];            // [layer][step][group][pad]

// ---------------- helpers ----------------
__device__ __forceinline__ int ld_acquire(const int* p) {
    int v;
    asm volatile("ld.global.acquire.gpu.b32 %0, [%1];" : "=r"(v) : "l"(p));
    return v;
}
__device__ __forceinline__ void red_release_add(int* p, int v) {
    asm volatile("red.release.gpu.global.add.u32 [%0], %1;" :: "l"(p), "r"(v) : "memory");
}
__device__ __forceinline__ float sigf(float x)  { return 1.f/(1.f + __expf(-x)); }
__device__ __forceinline__ float tanhf_(float x){ return 1.f - 2.f/(__expf(2.f*x) + 1.f); }
__device__ __forceinline__ uint32_t f2tf32(float f) {
    uint32_t u;
    asm("cvt.rna.tf32.f32 %0, %1;" : "=r"(u) : "f"(f));
    return u;
}
__device__ __forceinline__ void mma_tf32(float& c0, float& c1, float& c2, float& c3,
                                         uint32_t a0, uint32_t a1, uint32_t a2, uint32_t a3,
                                         uint32_t b0, uint32_t b1) {
    asm volatile("mma.sync.aligned.m16n8k8.row.col.f32.tf32.tf32.f32 "
                 "{%0,%1,%2,%3}, {%4,%5,%6,%7}, {%8,%9}, {%0,%1,%2,%3};"
                 : "+f"(c0), "+f"(c1), "+f"(c2), "+f"(c3)
                 : "r"(a0), "r"(a1), "r"(a2), "r"(a3), "r"(b0), "r"(b1));
}

// ---------------- init ----------------
__global__ void init_kernel() {
    int i = blockIdx.x * blockDim.x + threadIdx.x;
    if (i < 2*2*HID*BATCH) {
        (&g_h1[0][0][0][0])[i] = 0.f;
        (&g_h2[0][0][0][0])[i] = 0.f;
    }
    if (i < 2*SEQ*4*8) (&g_bar[0][0][0][0])[i] = 0;
}

// ---------------- embedding ----------------
__global__ void embed_kernel(const int* __restrict__ words, const float* __restrict__ emb) {
    int row = blockIdx.x * 8 + (threadIdx.x >> 5);
    int lane = threadIdx.x & 31;
    int w = words[row];
    const float4* src = (const float4*)(emb + (size_t)w * EMB);
    float4*       dst = (float4*)(g_x + (size_t)row * EMB);
    dst[lane] = src[lane];
}

// ---------------- tf32 tensor-core dual GEMM (unchanged) ----------------
__global__ __launch_bounds__(256) void gemm_tf32_dual(
    const float* __restrict__ A,
    const float* __restrict__ Bw_f, const float* __restrict__ Bw_b,
    const float* __restrict__ b1f, const float* __restrict__ b2f,
    const float* __restrict__ b1b, const float* __restrict__ b2b,
    float* __restrict__ Cf, float* __restrict__ Cb,
    int M, int N, int K)
{
    const float* Bw    = blockIdx.z ? Bw_b : Bw_f;
    const float* bias1 = blockIdx.z ? b1b  : b1f;
    const float* bias2 = blockIdx.z ? b2b  : b2f;
    float*       C     = blockIdx.z ? Cb   : Cf;

    __shared__ uint32_t As[2][128][20];
    __shared__ uint32_t Bs[2][128][20];

    const int tid  = threadIdx.x;
    const int lane = tid & 31;
    const int warp = tid >> 5;
    const int m0 = blockIdx.y * 128;
    const int n0 = blockIdx.x * 128;
    const int wm = (warp >> 2) * 64;
    const int wn = (warp & 3) * 32;
    const int ar = lane >> 2;
    const int ac = lane & 3;

    const int lr = tid >> 2;
    const int lk = (tid & 3) * 4;
    const float* Aptr0 = A  + (size_t)(m0 + lr)      * K + lk;
    const float* Aptr1 = A  + (size_t)(m0 + 64 + lr) * K + lk;
    const float* Bptr0 = Bw + (size_t)(n0 + lr)      * K + lk;
    const float* Bptr1 = Bw + (size_t)(n0 + 64 + lr) * K + lk;

    float c[4][4][4];
    #pragma unroll
    for (int i = 0; i < 4; i++)
        #pragma unroll
        for (int j = 0; j < 4; j++)
            #pragma unroll
            for (int r = 0; r < 4; r++) c[i][j][r] = 0.f;

    {
        float4 a0 = *(const float4*)Aptr0;
        float4 a1 = *(const float4*)Aptr1;
        float4 b0 = *(const float4*)Bptr0;
        float4 b1 = *(const float4*)Bptr1;
        As[0][lr][lk+0]=f2tf32(a0.x); As[0][lr][lk+1]=f2tf32(a0.y); As[0][lr][lk+2]=f2tf32(a0.z); As[0][lr][lk+3]=f2tf32(a0.w);
        As[0][64+lr][lk+0]=f2tf32(a1.x); As[0][64+lr][lk+1]=f2tf32(a1.y); As[0][64+lr][lk+2]=f2tf32(a1.z); As[0][64+lr][lk+3]=f2tf32(a1.w);
        Bs[0][lr][lk+0]=f2tf32(b0.x); Bs[0][lr][lk+1]=f2tf32(b0.y); Bs[0][lr][lk+2]=f2tf32(b0.z); Bs[0][lr][lk+3]=f2tf32(b0.w);
        Bs[0][64+lr][lk+0]=f2tf32(b1.x); Bs[0][64+lr][lk+1]=f2tf32(b1.y); Bs[0][64+lr][lk+2]=f2tf32(b1.z); Bs[0][64+lr][lk+3]=f2tf32(b1.w);
    }
    __syncthreads();

    const int T = K / 16;
    float4 pa0, pa1, pb0, pb1;
    for (int tI = 0; tI < T; tI++) {
        const int buf = tI & 1;
        const bool more = (tI + 1 < T);
        if (more) {
            const int off = (tI + 1) * 16;
            pa0 = *(const float4*)(Aptr0 + off);
            pa1 = *(const float4*)(Aptr1 + off);
            pb0 = *(const float4*)(Bptr0 + off);
            pb1 = *(const float4*)(Bptr1 + off);
        }

        #pragma unroll
        for (int kb = 0; kb < 16; kb += 8) {
            uint32_t afr[4][4];
            #pragma unroll
            for (int i = 0; i < 4; i++) {
                int mrow = wm + i*16 + ar;
                afr[i][0] = As[buf][mrow    ][kb + ac];
                afr[i][1] = As[buf][mrow + 8][kb + ac];
                afr[i][2] = As[buf][mrow    ][kb + ac + 4];
                afr[i][3] = As[buf][mrow + 8][kb + ac + 4];
            }
            uint32_t bfr[4][2];
            #pragma unroll
            for (int j = 0; j < 4; j++) {
                int nrow = wn + j*8 + ar;
                bfr[j][0] = Bs[buf][nrow][kb + ac];
                bfr[j][1] = Bs[buf][nrow][kb + ac + 4];
            }
            #pragma unroll
            for (int i = 0; i < 4; i++)
                #pragma unroll
                for (int j = 0; j < 4; j++)
                    mma_tf32(c[i][j][0], c[i][j][1], c[i][j][2], c[i][j][3],
                             afr[i][0], afr[i][1], afr[i][2], afr[i][3],
                             bfr[j][0], bfr[j][1]);
        }

        if (more) {
            const int nb = buf ^ 1;
            __syncthreads();
            As[nb][lr][lk+0]=f2tf32(pa0.x); As[nb][lr][lk+1]=f2tf32(pa0.y); As[nb][lr][lk+2]=f2tf32(pa0.z); As[nb][lr][lk+3]=f2tf32(pa0.w);
            As[nb][64+lr][lk+0]=f2tf32(pa1.x); As[nb][64+lr][lk+1]=f2tf32(pa1.y); As[nb][64+lr][lk+2]=f2tf32(pa1.z); As[nb][64+lr][lk+3]=f2tf32(pa1.w);
            Bs[nb][lr][lk+0]=f2tf32(pb0.x); Bs[nb][lr][lk+1]=f2tf32(pb0.y); Bs[nb][lr][lk+2]=f2tf32(pb0.z); Bs[nb][lr][lk+3]=f2tf32(pb0.w);
            Bs[nb][64+lr][lk+0]=f2tf32(pb1.x); Bs[nb][64+lr][lk+1]=f2tf32(pb1.y); Bs[nb][64+lr][lk+2]=f2tf32(pb1.z); Bs[nb][64+lr][lk+3]=f2tf32(pb1.w);
            __syncthreads();
        }
    }

    #pragma unroll
    for (int i = 0; i < 4; i++) {
        int row0 = m0 + wm + i*16 + ar;
        #pragma unroll
        for (int j = 0; j < 4; j++) {
            int col = n0 + wn + j*8 + 2*ac;
            float bsum0 = bias1[col]   + (bias2 ? bias2[col]   : 0.f);
            float bsum1 = bias1[col+1] + (bias2 ? bias2[col+1] : 0.f);
            *(float2*)(C + (size_t)row0 * N + col)       = make_float2(c[i][j][0] + bsum0, c[i][j][1] + bsum1);
            *(float2*)(C + (size_t)(row0 + 8) * N + col) = make_float2(c[i][j][2] + bsum0, c[i][j][3] + bsum1);
        }
    }
}

// ---------------- fp32 SIMT classifier GEMM (unchanged) ----------------
__global__ __launch_bounds__(256) void sgemm_cls_kernel(
    const float* __restrict__ A, const float* __restrict__ Bw,
    const float* __restrict__ bias1,
    float* __restrict__ C, int M, int N, int K)
{
    const int BM = 128, BN = 128, BK = 16;
    __shared__ float As[2][BK][BM];
    __shared__ float Bs[2][BK][BN];

    const int tid = threadIdx.x;
    const int m0 = blockIdx.y * BM;
    const int n0 = blockIdx.x * BN;
    const int ty = tid >> 4;
    const int tx = tid & 15;

    const int lr = tid >> 2;
    const int lk = (tid & 3) * 4;
    const float* Aptr0 = A + (size_t)(m0 + lr)      * K + lk;
    const float* Aptr1 = A + (size_t)(m0 + 64 + lr) * K + lk;
    const int bn0 = n0 + lr, bn1 = n0 + 64 + lr;
    const float* Bptr0 = Bw + (size_t)bn0 * K + lk;
    const float* Bptr1 = Bw + (size_t)bn1 * K + lk;
    const bool b0ok = bn0 < N, b1ok = bn1 < N;

    float acc[8][8];
    #pragma unroll
    for (int i = 0; i < 8; i++)
        #pragma unroll
        for (int j = 0; j < 8; j++) acc[i][j] = 0.f;

    const float4 z4 = make_float4(0.f,0.f,0.f,0.f);
    float4 av0, av1, bv0, bv1;

    av0 = *(const float4*)Aptr0;
    av1 = *(const float4*)Aptr1;
    bv0 = b0ok ? *(const float4*)Bptr0 : z4;
    bv1 = b1ok ? *(const float4*)Bptr1 : z4;
    As[0][lk+0][lr] = av0.x; As[0][lk+1][lr] = av0.y; As[0][lk+2][lr] = av0.z; As[0][lk+3][lr] = av0.w;
    As[0][lk+0][64+lr] = av1.x; As[0][lk+1][64+lr] = av1.y; As[0][lk+2][64+lr] = av1.z; As[0][lk+3][64+lr] = av1.w;
    Bs[0][lk+0][lr] = bv0.x; Bs[0][lk+1][lr] = bv0.y; Bs[0][lk+2][lr] = bv0.z; Bs[0][lk+3][lr] = bv0.w;
    Bs[0][lk+0][64+lr] = bv1.x; Bs[0][lk+1][64+lr] = bv1.y; Bs[0][lk+2][64+lr] = bv1.z; Bs[0][lk+3][64+lr] = bv1.w;
    __syncthreads();

    const int T = K / BK;
    for (int tI = 0; tI < T; tI++) {
        const int buf = tI & 1;
        const bool more = (tI + 1 < T);
        if (more) {
            const int off = (tI + 1) * BK;
            av0 = *(const float4*)(Aptr0 + off);
            av1 = *(const float4*)(Aptr1 + off);
            bv0 = b0ok ? *(const float4*)(Bptr0 + off) : z4;
            bv1 = b1ok ? *(const float4*)(Bptr1 + off) : z4;
        }
        #pragma unroll
        for (int k = 0; k < BK; k++) {
            float4 a0 = *(const float4*)&As[buf][k][ty*8];
            float4 a1 = *(const float4*)&As[buf][k][ty*8+4];
            float4 b0 = *(const float4*)&Bs[buf][k][tx*8];
            float4 b1 = *(const float4*)&Bs[buf][k][tx*8+4];
            float ar[8] = {a0.x,a0.y,a0.z,a0.w,a1.x,a1.y,a1.z,a1.w};
            float br[8] = {b0.x,b0.y,b0.z,b0.w,b1.x,b1.y,b1.z,b1.w};
            #pragma unroll
            for (int i = 0; i < 8; i++)
                #pragma unroll
                for (int j = 0; j < 8; j++)
                    acc[i][j] = fmaf(ar[i], br[j], acc[i][j]);
        }
        if (more) {
            const int nb = buf ^ 1;
            __syncthreads();
            As[nb][lk+0][lr] = av0.x; As[nb][lk+1][lr] = av0.y; As[nb][lk+2][lr] = av0.z; As[nb][lk+3][lr] = av0.w;
            As[nb][lk+0][64+lr] = av1.x; As[nb][lk+1][64+lr] = av1.y; As[nb][lk+2][64+lr] = av1.z; As[nb][lk+3][64+lr] = av1.w;
            Bs[nb][lk+0][lr] = bv0.x; Bs[nb][lk+1][lr] = bv0.y; Bs[nb][lk+2][lr] = bv0.z; Bs[nb][lk+3][lr] = bv0.w;
            Bs[nb][lk+0][64+lr] = bv1.x; Bs[nb][lk+1][64+lr] = bv1.y; Bs[nb][lk+2][64+lr] = bv1.z; Bs[nb][lk+3][64+lr] = bv1.w;
            __syncthreads();
        }
    }

    #pragma unroll
    for (int i = 0; i < 8; i++) {
        int m = m0 + ty*8 + i;
        #pragma unroll
        for (int j = 0; j < 8; j++) {
            int n = n0 + tx*8 + j;
            if (n < N) C[(size_t)m * N + n] = acc[i][j] + bias1[n];
        }
    }
}

// ---------------- persistent BiLSTM recurrence: R9 structure (proven), raw-fp32 staging ----
// 128 blocks = dir(2) x jslice(32, 8 j each) x bhalf(2, 32 b each); 256 threads (8 warps).
// Warp w: mw=w&1 (m-tile), nw2=(w>>1)&1 (16-batch group), kh=w>>2 (128-k half).
// Whh resident in regs. h staged per step to smem as raw fp32 (mma truncates to tf32);
// masked pass-through uses the block's own exact hst. Barrier exactly as R9.
// SMEM floats: ht 256*40=10240, part 2*32*33=2112, xg 32*33=1056, hst 256, lens 32 = 13696
#define SMEM_RECUR (13696 * 4)

__global__ __launch_bounds__(256, 1) void recur_kernel(
    const float* __restrict__ xg_f, const float* __restrict__ xg_b,
    const float* __restrict__ Whh_f, const float* __restrict__ Whh_b,
    const int* __restrict__ lengths, float* __restrict__ out,
    float* __restrict__ hbuf, int* __restrict__ bar)
{
    extern __shared__ float smem[];
    float* ht     = smem;                    // [256 k][40] raw fp32
    float* part   = smem + 10240;            // [2 kh][32 r][33]
    float* xg_sm  = smem + 12352;            // [32 b][33]
    float* hst    = smem + 13408;            // [8 jj][32 b]  (this block's fp32 h)
    int*   lens_sm= (int*)(smem + 13664);    // [32]

    const int tid  = threadIdx.x;
    const int lane = tid & 31;
    const int warp = tid >> 5;
    const int blk = blockIdx.x;
    const int dir    = blk >> 6;
    const int jslice = (blk >> 1) & 31;
    const int bh     = blk & 1;
    const int j0 = jslice * 8;
    const int b0 = bh * 32;
    const int grp = dir * 2 + bh;
    const float* Whh = dir ? Whh_b : Whh_f;
    const float* xg  = dir ? xg_b  : xg_f;

    // warp mma coordinates
    const int mw  = warp & 1;
    const int nw2 = (warp >> 1) & 1;
    const int kh  = warp >> 2;
    const int lg  = lane >> 2;
    const int lc  = lane & 3;
    const int bcol0 = 16*nw2 + lg;
    const int khbase = kh * 128;

    // one-time Whh A-fragment load (resident all steps)
    uint32_t wfrag[16][4];
    #pragma unroll
    for (int ka = 0; ka < 16; ka++) {
        #pragma unroll
        for (int i = 0; i < 4; i++) {
            int r   = 16*mw + lg + (i & 1) * 8;
            int col = khbase + ka*8 + lc + (i >> 1) * 4;
            int g = r >> 3, jj = r & 7;
            wfrag[ka][i] = f2tf32(Whh[(size_t)(g*HID + j0 + jj) * HID + col]);
        }
    }
    if (tid < 32) lens_sm[tid] = lengths[b0 + tid];
    hst[tid] = 0.f;                      // h(s=0) = 0

    // xg staging mapping
    const int sb    = tid >> 3;
    const int sg    = (tid >> 1) & 3;
    const int shalf = tid & 1;
    const size_t xg_row_base = ((size_t)(b0 + sb) * SEQ);
    const int xg_col = sg*HID + j0 + shalf*4;

    // combine mapping
    const int rr = tid >> 5;
    const int cb = tid & 31;
    float c_reg = 0.f;

    __syncthreads();

    int t0 = dir ? (SEQ - 1) : 0;
    float4 xg_pf = __ldg((const float4*)(xg + (xg_row_base + t0) * G4 + xg_col));

    for (int s = 0; s < SEQ; s++) {
        const int t = dir ? (SEQ - 1 - s) : s;

        if (s > 0) {
            if (tid == 0) {
                int* cnt = bar + ((s-1)*4 + grp)*8;
                while (ld_acquire(cnt) < GRP_BLOCKS) __nanosleep(40);
            }
            __syncthreads();
        }

        // stage xg + h (raw fp32; mma truncates to tf32) + prefetch next xg
        {
            float* xd = xg_sm + sb*33 + sg*8 + shalf*4;
            xd[0] = xg_pf.x; xd[1] = xg_pf.y; xd[2] = xg_pf.z; xd[3] = xg_pf.w;

            const float* hsrc = hbuf + (size_t)((s & 1)*2 + dir) * HID * BATCH;
            #pragma unroll
            for (int n = 0; n < 8; n++) {
                int i = tid + n*256;                 // 0..2047
                int k = i >> 3, o = (i & 7)*4;
                float4 v = __ldcg((const float4*)(hsrc + k*BATCH + b0 + o));
                *(float4*)(ht + k*HSTRIDE + o) = v;
            }

            if (s + 1 < SEQ) {
                int tn = dir ? (SEQ - 2 - s) : (s + 1);
                xg_pf = __ldg((const float4*)(xg + (xg_row_base + tn) * G4 + xg_col));
            }
        }
        __syncthreads();

        // tensor-core gate GEMM over this warp's k-half (B frags from smem)
        {
            float acc[2][4];
            #pragma unroll
            for (int na = 0; na < 2; na++)
                #pragma unroll
                for (int r = 0; r < 4; r++) acc[na][r] = 0.f;

            #pragma unroll
            for (int ka = 0; ka < 16; ka++) {
                const float* hp = ht + (khbase + ka*8 + lc)*HSTRIDE;
                #pragma unroll
                for (int na = 0; na < 2; na++) {
                    const int bc = bcol0 + na*8;
                    uint32_t bf0 = __float_as_uint(hp[bc]);
                    uint32_t bf1 = __float_as_uint(hp[4*HSTRIDE + bc]);
                    mma_tf32(acc[na][0], acc[na][1], acc[na][2], acc[na][3],
                             wfrag[ka][0], wfrag[ka][1], wfrag[ka][2], wfrag[ka][3],
                             bf0, bf1);
                }
            }

            float* pd = part + kh*1056;
            #pragma unroll
            for (int na = 0; na < 2; na++) {
                int col = 16*nw2 + na*8 + 2*lc;
                int row = 16*mw + lg;
                pd[row*33 + col]         = acc[na][0];
                pd[row*33 + col + 1]     = acc[na][1];
                pd[(row + 8)*33 + col]   = acc[na][2];
                pd[(row + 8)*33 + col+1] = acc[na][3];
            }
        }
        __syncthreads();

        // combine: thread = (jj=rr, b=cb); h_prev from our own previous hst (fp32-exact)
        {
            float gate[4];
            #pragma unroll
            for (int g = 0; g < 4; g++) {
                int r = g*8 + rr;
                gate[g] = part[r*33 + cb] + part[1056 + r*33 + cb]
                        + xg_sm[cb*33 + g*8 + rr];
            }
            float h_prev = hst[rr*32 + cb];
            float c_new = sigf(gate[1]) * c_reg + sigf(gate[0]) * tanhf_(gate[2]);
            float h_new = sigf(gate[3]) * tanhf_(c_new);
            bool  m = (t < lens_sm[cb]);
            float h_out = m ? h_new : h_prev;
            c_reg       = m ? c_new : c_reg;

            hbuf[(size_t)(((s+1) & 1)*2 + dir) * HID * BATCH + (j0 + rr)*BATCH + b0 + cb] = h_out;
            hst[rr*32 + cb] = h_out;
        }
        __syncthreads();
        if (tid == 0) red_release_add(bar + (s*4 + grp)*8, 1);

        // semi-coalesced out store (64 threads x float4)
        if (tid < 64) {
            int bb  = tid >> 1;
            int seg = tid & 1;
            float4 v;
            v.x = hst[(seg*4+0)*32 + bb];
            v.y = hst[(seg*4+1)*32 + bb];
            v.z = hst[(seg*4+2)*32 + bb];
            v.w = hst[(seg*4+3)*32 + bb];
            *(float4*)(out + ((size_t)(b0 + bb) * SEQ + t) * (2*HID) + dir*HID + j0 + seg*4) = v;
        }
    }
}

// ---------------- launch ----------------
extern "C" void kernel_launch(void* const* d_in, const int* in_sizes, int n_in,
                              void* d_out, int out_size)
{
    (void)in_sizes; (void)n_in; (void)out_size;
    const int*   words    = (const int*)  d_in[0];
    const int*   lengths  = (const int*)  d_in[1];
    const float* emb      = (const float*)d_in[2];
    const float* l1f_Wih  = (const float*)d_in[3];
    const float* l1f_Whh  = (const float*)d_in[4];
    const float* l1f_bih  = (const float*)d_in[5];
    const float* l1f_bhh  = (const float*)d_in[6];
    const float* l1b_Wih  = (const float*)d_in[7];
    const float* l1b_Whh  = (const float*)d_in[8];
    const float* l1b_bih  = (const float*)d_in[9];
    const float* l1b_bhh  = (const float*)d_in[10];
    const float* l2f_Wih  = (const float*)d_in[11];
    const float* l2f_Whh  = (const float*)d_in[12];
    const float* l2f_bih  = (const float*)d_in[13];
    const float* l2f_bhh  = (const float*)d_in[14];
    const float* l2b_Wih  = (const float*)d_in[15];
    const float* l2b_Whh  = (const float*)d_in[16];
    const float* l2b_bih  = (const float*)d_in[17];
    const float* l2b_bhh  = (const float*)d_in[18];
    const float* cls_W    = (const float*)d_in[19];
    const float* cls_b    = (const float*)d_in[20];
    float* out = (float*)d_out;

    float *px, *pxf, *pxb, *po1, *po2, *ph1, *ph2;
    int *pbar;
    cudaGetSymbolAddress((void**)&px,   g_x);
    cudaGetSymbolAddress((void**)&pxf,  g_xg_f);
    cudaGetSymbolAddress((void**)&pxb,  g_xg_b);
    cudaGetSymbolAddress((void**)&po1,  g_o1);
    cudaGetSymbolAddress((void**)&po2,  g_o2);
    cudaGetSymbolAddress((void**)&ph1,  g_h1);
    cudaGetSymbolAddress((void**)&ph2,  g_h2);
    cudaGetSymbolAddress((void**)&pbar, g_bar);

    cudaFuncSetAttribute(recur_kernel, cudaFuncAttributeMaxDynamicSharedMemorySize, SMEM_RECUR);

    // 1) init
    init_kernel<<<256, 256>>>();

    // 2) embedding
    embed_kernel<<<M_ROWS/8, 256>>>(words, emb);

    // 3) layer-1 input projections
    dim3 gx(G4/128, M_ROWS/128, 2);
    gemm_tf32_dual<<<gx, 256>>>(px, l1f_Wih, l1b_Wih,
                                l1f_bih, l1f_bhh, l1b_bih, l1b_bhh,
                                pxf, pxb, M_ROWS, G4, EMB);

    // 4) layer-1 recurrence
    recur_kernel<<<REC_BLOCKS, 256, SMEM_RECUR>>>(pxf, pxb, l1f_Whh, l1b_Whh,
                                                  lengths, po1, ph1, pbar);

    // 5) layer-2 input projections
    gemm_tf32_dual<<<gx, 256>>>(po1, l2f_Wih, l2b_Wih,
                                l2f_bih, l2f_bhh, l2b_bih, l2b_bhh,
                                pxf, pxb, M_ROWS, G4, 2*HID);

    // 6) layer-2 recurrence
    recur_kernel<<<REC_BLOCKS, 256, SMEM_RECUR>>>(pxf, pxb, l2f_Whh, l2b_Whh,
                                                  lengths, po2, ph2, pbar + SEQ*4*8);

    // 7) classifier (fp32)
    dim3 gc(1, M_ROWS/128, 1);
    sgemm_cls_kernel<<<gc, 256>>>(po2, cls_W, cls_b, out, M_ROWS, NTAGS, 2*HID);
}

// round 16
// speedup vs baseline: 1.4569x; 1.0430x over previous
#include <cuda_runtime.h>
#include <cstdint>

#define BATCH 64
#define SEQ   512
#define EMB   128
#define HID   256
#define G4    1024            // 4*HID
#define NTAGS 50
#define M_ROWS (BATCH*SEQ)    // 32768
#define REC_BLOCKS 128        // 2 dirs * 32 j-slices * 2 batch-halves
#define GRP_BLOCKS 32         // blocks per (dir, bhalf) barrier group
#define HSTRIDE 40            // smem row stride (floats) for conflict-free B frags

// ---------------- scratch (device globals; allocation-free) ----------------
__device__ float g_x   [(size_t)M_ROWS*EMB];
__device__ float g_xg_f[(size_t)M_ROWS*G4];
__device__ float g_xg_b[(size_t)M_ROWS*G4];
__device__ float g_o1  [(size_t)M_ROWS*2*HID];
__device__ float g_o2  [(size_t)M_ROWS*2*HID];
__device__ float g_h1  [2][2][HID][BATCH];        // [parity][dir][k][b]
__device__ float g_h2  [2][2][HID][BATCH];
__device__ int   g_bar [2][SEQ][4][8];            // [layer][step][group][pad]

// ---------------- helpers ----------------
__device__ __forceinline__ int ld_acquire(const int* p) {
    int v;
    asm volatile("ld.global.acquire.gpu.b32 %0, [%1];" : "=r"(v) : "l"(p));
    return v;
}
__device__ __forceinline__ void red_release_add(int* p, int v) {
    asm volatile("red.release.gpu.global.add.u32 [%0], %1;" :: "l"(p), "r"(v) : "memory");
}
__device__ __forceinline__ float sigf(float x)  { return 1.f/(1.f + __expf(-x)); }
__device__ __forceinline__ float tanhf_(float x){ return 1.f - 2.f/(__expf(2.f*x) + 1.f); }
__device__ __forceinline__ uint32_t f2tf32(float f) {
    uint32_t u;
    asm("cvt.rna.tf32.f32 %0, %1;" : "=r"(u) : "f"(f));
    return u;
}
__device__ __forceinline__ void mma_tf32(float& c0, float& c1, float& c2, float& c3,
                                         uint32_t a0, uint32_t a1, uint32_t a2, uint32_t a3,
                                         uint32_t b0, uint32_t b1) {
    asm volatile("mma.sync.aligned.m16n8k8.row.col.f32.tf32.tf32.f32 "
                 "{%0,%1,%2,%3}, {%4,%5,%6,%7}, {%8,%9}, {%0,%1,%2,%3};"
                 : "+f"(c0), "+f"(c1), "+f"(c2), "+f"(c3)
                 : "r"(a0), "r"(a1), "r"(a2), "r"(a3), "r"(b0), "r"(b1));
}

// ---------------- init ----------------
__global__ void init_kernel() {
    int i = blockIdx.x * blockDim.x + threadIdx.x;
    if (i < 2*2*HID*BATCH) {
        (&g_h1[0][0][0][0])[i] = 0.f;
        (&g_h2[0][0][0][0])[i] = 0.f;
    }
    if (i < 2*SEQ*4*8) (&g_bar[0][0][0][0])[i] = 0;
}

// ---------------- embedding ----------------
__global__ void embed_kernel(const int* __restrict__ words, const float* __restrict__ emb) {
    int row = blockIdx.x * 8 + (threadIdx.x >> 5);
    int lane = threadIdx.x & 31;
    int w = words[row];
    const float4* src = (const float4*)(emb + (size_t)w * EMB);
    float4*       dst = (float4*)(g_x + (size_t)row * EMB);
    dst[lane] = src[lane];
}

// ---------------- tf32 tensor-core dual GEMM ----------------
__global__ __launch_bounds__(256) void gemm_tf32_dual(
    const float* __restrict__ A,
    const float* __restrict__ Bw_f, const float* __restrict__ Bw_b,
    const float* __restrict__ b1f, const float* __restrict__ b2f,
    const float* __restrict__ b1b, const float* __restrict__ b2b,
    float* __restrict__ Cf, float* __restrict__ Cb,
    int M, int N, int K)
{
    const float* Bw    = blockIdx.z ? Bw_b : Bw_f;
    const float* bias1 = blockIdx.z ? b1b  : b1f;
    const float* bias2 = blockIdx.z ? b2b  : b2f;
    float*       C     = blockIdx.z ? Cb   : Cf;

    __shared__ uint32_t As[2][128][20];
    __shared__ uint32_t Bs[2][128][20];

    const int tid  = threadIdx.x;
    const int lane = tid & 31;
    const int warp = tid >> 5;
    const int m0 = blockIdx.y * 128;
    const int n0 = blockIdx.x * 128;
    const int wm = (warp >> 2) * 64;
    const int wn = (warp & 3) * 32;
    const int ar = lane >> 2;
    const int ac = lane & 3;

    const int lr = tid >> 2;
    const int lk = (tid & 3) * 4;
    const float* Aptr0 = A  + (size_t)(m0 + lr)      * K + lk;
    const float* Aptr1 = A  + (size_t)(m0 + 64 + lr) * K + lk;
    const float* Bptr0 = Bw + (size_t)(n0 + lr)      * K + lk;
    const float* Bptr1 = Bw + (size_t)(n0 + 64 + lr) * K + lk;

    float c[4][4][4];
    #pragma unroll
    for (int i = 0; i < 4; i++)
        #pragma unroll
        for (int j = 0; j < 4; j++)
            #pragma unroll
            for (int r = 0; r < 4; r++) c[i][j][r] = 0.f;

    {
        float4 a0 = *(const float4*)Aptr0;
        float4 a1 = *(const float4*)Aptr1;
        float4 b0 = *(const float4*)Bptr0;
        float4 b1 = *(const float4*)Bptr1;
        As[0][lr][lk+0]=f2tf32(a0.x); As[0][lr][lk+1]=f2tf32(a0.y); As[0][lr][lk+2]=f2tf32(a0.z); As[0][lr][lk+3]=f2tf32(a0.w);
        As[0][64+lr][lk+0]=f2tf32(a1.x); As[0][64+lr][lk+1]=f2tf32(a1.y); As[0][64+lr][lk+2]=f2tf32(a1.z); As[0][64+lr][lk+3]=f2tf32(a1.w);
        Bs[0][lr][lk+0]=f2tf32(b0.x); Bs[0][lr][lk+1]=f2tf32(b0.y); Bs[0][lr][lk+2]=f2tf32(b0.z); Bs[0][lr][lk+3]=f2tf32(b0.w);
        Bs[0][64+lr][lk+0]=f2tf32(b1.x); Bs[0][64+lr][lk+1]=f2tf32(b1.y); Bs[0][64+lr][lk+2]=f2tf32(b1.z); Bs[0][64+lr][lk+3]=f2tf32(b1.w);
    }
    __syncthreads();

    const int T = K / 16;
    float4 pa0, pa1, pb0, pb1;
    for (int tI = 0; tI < T; tI++) {
        const int buf = tI & 1;
        const bool more = (tI + 1 < T);
        if (more) {
            const int off = (tI + 1) * 16;
            pa0 = *(const float4*)(Aptr0 + off);
            pa1 = *(const float4*)(Aptr1 + off);
            pb0 = *(const float4*)(Bptr0 + off);
            pb1 = *(const float4*)(Bptr1 + off);
        }

        #pragma unroll
        for (int kb = 0; kb < 16; kb += 8) {
            uint32_t afr[4][4];
            #pragma unroll
            for (int i = 0; i < 4; i++) {
                int mrow = wm + i*16 + ar;
                afr[i][0] = As[buf][mrow    ][kb + ac];
                afr[i][1] = As[buf][mrow + 8][kb + ac];
                afr[i][2] = As[buf][mrow    ][kb + ac + 4];
                afr[i][3] = As[buf][mrow + 8][kb + ac + 4];
            }
            uint32_t bfr[4][2];
            #pragma unroll
            for (int j = 0; j < 4; j++) {
                int nrow = wn + j*8 + ar;
                bfr[j][0] = Bs[buf][nrow][kb + ac];
                bfr[j][1] = Bs[buf][nrow][kb + ac + 4];
            }
            #pragma unroll
            for (int i = 0; i < 4; i++)
                #pragma unroll
                for (int j = 0; j < 4; j++)
                    mma_tf32(c[i][j][0], c[i][j][1], c[i][j][2], c[i][j][3],
                             afr[i][0], afr[i][1], afr[i][2], afr[i][3],
                             bfr[j][0], bfr[j][1]);
        }

        if (more) {
            const int nb = buf ^ 1;
            __syncthreads();
            As[nb][lr][lk+0]=f2tf32(pa0.x); As[nb][lr][lk+1]=f2tf32(pa0.y); As[nb][lr][lk+2]=f2tf32(pa0.z); As[nb][lr][lk+3]=f2tf32(pa0.w);
            As[nb][64+lr][lk+0]=f2tf32(pa1.x); As[nb][64+lr][lk+1]=f2tf32(pa1.y); As[nb][64+lr][lk+2]=f2tf32(pa1.z); As[nb][64+lr][lk+3]=f2tf32(pa1.w);
            Bs[nb][lr][lk+0]=f2tf32(pb0.x); Bs[nb][lr][lk+1]=f2tf32(pb0.y); Bs[nb][lr][lk+2]=f2tf32(pb0.z); Bs[nb][lr][lk+3]=f2tf32(pb0.w);
            Bs[nb][64+lr][lk+0]=f2tf32(pb1.x); Bs[nb][64+lr][lk+1]=f2tf32(pb1.y); Bs[nb][64+lr][lk+2]=f2tf32(pb1.z); Bs[nb][64+lr][lk+3]=f2tf32(pb1.w);
            __syncthreads();
        }
    }

    #pragma unroll
    for (int i = 0; i < 4; i++) {
        int row0 = m0 + wm + i*16 + ar;
        #pragma unroll
        for (int j = 0; j < 4; j++) {
            int col = n0 + wn + j*8 + 2*ac;
            float bsum0 = bias1[col]   + (bias2 ? bias2[col]   : 0.f);
            float bsum1 = bias1[col+1] + (bias2 ? bias2[col+1] : 0.f);
            *(float2*)(C + (size_t)row0 * N + col)       = make_float2(c[i][j][0] + bsum0, c[i][j][1] + bsum1);
            *(float2*)(C + (size_t)(row0 + 8) * N + col) = make_float2(c[i][j][2] + bsum0, c[i][j][3] + bsum1);
        }
    }
}

// ---------------- tf32 tensor-core classifier GEMM (N=50 guarded) ----------------
__global__ __launch_bounds__(256) void gemm_tf32_cls(
    const float* __restrict__ A, const float* __restrict__ Bw,
    const float* __restrict__ bias1,
    float* __restrict__ C, int M, int N, int K)
{
    __shared__ uint32_t As[2][128][20];
    __shared__ uint32_t Bs[2][128][20];

    const int tid  = threadIdx.x;
    const int lane = tid & 31;
    const int warp = tid >> 5;
    const int m0 = blockIdx.y * 128;
    const int wm = (warp >> 2) * 64;
    const int wn = (warp & 3) * 32;
    const int ar = lane >> 2;
    const int ac = lane & 3;

    const int lr = tid >> 2;
    const int lk = (tid & 3) * 4;
    const float* Aptr0 = A  + (size_t)(m0 + lr)      * K + lk;
    const float* Aptr1 = A  + (size_t)(m0 + 64 + lr) * K + lk;
    const bool b0ok = lr < N;              // n0 = 0 (single N tile)
    const bool b1ok = (64 + lr) < N;
    const float* Bptr0 = Bw + (size_t)lr        * K + lk;
    const float* Bptr1 = Bw + (size_t)(64 + lr) * K + lk;
    const float4 z4 = make_float4(0.f,0.f,0.f,0.f);

    float c[4][4][4];
    #pragma unroll
    for (int i = 0; i < 4; i++)
        #pragma unroll
        for (int j = 0; j < 4; j++)
            #pragma unroll
            for (int r = 0; r < 4; r++) c[i][j][r] = 0.f;

    {
        float4 a0 = *(const float4*)Aptr0;
        float4 a1 = *(const float4*)Aptr1;
        float4 b0 = b0ok ? *(const float4*)Bptr0 : z4;
        float4 b1 = b1ok ? *(const float4*)Bptr1 : z4;
        As[0][lr][lk+0]=f2tf32(a0.x); As[0][lr][lk+1]=f2tf32(a0.y); As[0][lr][lk+2]=f2tf32(a0.z); As[0][lr][lk+3]=f2tf32(a0.w);
        As[0][64+lr][lk+0]=f2tf32(a1.x); As[0][64+lr][lk+1]=f2tf32(a1.y); As[0][64+lr][lk+2]=f2tf32(a1.z); As[0][64+lr][lk+3]=f2tf32(a1.w);
        Bs[0][lr][lk+0]=f2tf32(b0.x); Bs[0][lr][lk+1]=f2tf32(b0.y); Bs[0][lr][lk+2]=f2tf32(b0.z); Bs[0][lr][lk+3]=f2tf32(b0.w);
        Bs[0][64+lr][lk+0]=f2tf32(b1.x); Bs[0][64+lr][lk+1]=f2tf32(b1.y); Bs[0][64+lr][lk+2]=f2tf32(b1.z); Bs[0][64+lr][lk+3]=f2tf32(b1.w);
    }
    __syncthreads();

    const int T = K / 16;
    float4 pa0, pa1, pb0, pb1;
    for (int tI = 0; tI < T; tI++) {
        const int buf = tI & 1;
        const bool more = (tI + 1 < T);
        if (more) {
            const int off = (tI + 1) * 16;
            pa0 = *(const float4*)(Aptr0 + off);
            pa1 = *(const float4*)(Aptr1 + off);
            pb0 = b0ok ? *(const float4*)(Bptr0 + off) : z4;
            pb1 = b1ok ? *(const float4*)(Bptr1 + off) : z4;
        }

        #pragma unroll
        for (int kb = 0; kb < 16; kb += 8) {
            uint32_t afr[4][4];
            #pragma unroll
            for (int i = 0; i < 4; i++) {
                int mrow = wm + i*16 + ar;
                afr[i][0] = As[buf][mrow    ][kb + ac];
                afr[i][1] = As[buf][mrow + 8][kb + ac];
                afr[i][2] = As[buf][mrow    ][kb + ac + 4];
                afr[i][3] = As[buf][mrow + 8][kb + ac + 4];
            }
            uint32_t bfr[4][2];
            #pragma unroll
            for (int j = 0; j < 4; j++) {
                int nrow = wn + j*8 + ar;
                bfr[j][0] = Bs[buf][nrow][kb + ac];
                bfr[j][1] = Bs[buf][nrow][kb + ac + 4];
            }
            #pragma unroll
            for (int i = 0; i < 4; i++)
                #pragma unroll
                for (int j = 0; j < 4; j++)
                    mma_tf32(c[i][j][0], c[i][j][1], c[i][j][2], c[i][j][3],
                             afr[i][0], afr[i][1], afr[i][2], afr[i][3],
                             bfr[j][0], bfr[j][1]);
        }

        if (more) {
            const int nb = buf ^ 1;
            __syncthreads();
            As[nb][lr][lk+0]=f2tf32(pa0.x); As[nb][lr][lk+1]=f2tf32(pa0.y); As[nb][lr][lk+2]=f2tf32(pa0.z); As[nb][lr][lk+3]=f2tf32(pa0.w);
            As[nb][64+lr][lk+0]=f2tf32(pa1.x); As[nb][64+lr][lk+1]=f2tf32(pa1.y); As[nb][64+lr][lk+2]=f2tf32(pa1.z); As[nb][64+lr][lk+3]=f2tf32(pa1.w);
            Bs[nb][lr][lk+0]=f2tf32(pb0.x); Bs[nb][lr][lk+1]=f2tf32(pb0.y); Bs[nb][lr][lk+2]=f2tf32(pb0.z); Bs[nb][lr][lk+3]=f2tf32(pb0.w);
            Bs[nb][64+lr][lk+0]=f2tf32(pb1.x); Bs[nb][64+lr][lk+1]=f2tf32(pb1.y); Bs[nb][64+lr][lk+2]=f2tf32(pb1.z); Bs[nb][64+lr][lk+3]=f2tf32(pb1.w);
            __syncthreads();
        }
    }

    #pragma unroll
    for (int i = 0; i < 4; i++) {
        int row0 = m0 + wm + i*16 + ar;
        #pragma unroll
        for (int j = 0; j < 4; j++) {
            int col = wn + j*8 + 2*ac;
            if (col < N) {   // N even, col even -> col+1 < N too
                float bsum0 = bias1[col];
                float bsum1 = bias1[col+1];
                *(float2*)(C + (size_t)row0 * N + col)       = make_float2(c[i][j][0] + bsum0, c[i][j][1] + bsum1);
                *(float2*)(C + (size_t)(row0 + 8) * N + col) = make_float2(c[i][j][2] + bsum0, c[i][j][3] + bsum1);
            }
        }
    }
}

// ---------------- persistent BiLSTM recurrence: R13 structure + length-based step skip ----
// 128 blocks = dir(2) x jslice(32, 8 j each) x bhalf(2, 32 b each); 256 threads (8 warps).
// Fully-masked steps (t >= group max length) skip barrier/stage/mma and just emit hst.
// SMEM floats: ht 256*40=10240, part 2*32*33=2112, xg 32*33=1056, hst 256, lens 32 = 13696
#define SMEM_RECUR (13696 * 4)

__global__ __launch_bounds__(256, 1) void recur_kernel(
    const float* __restrict__ xg_f, const float* __restrict__ xg_b,
    const float* __restrict__ Whh_f, const float* __restrict__ Whh_b,
    const int* __restrict__ lengths, float* __restrict__ out,
    float* __restrict__ hbuf, int* __restrict__ bar)
{
    extern __shared__ float smem[];
    float* ht     = smem;                    // [256 k][40] raw fp32
    float* part   = smem + 10240;            // [2 kh][32 r][33]
    float* xg_sm  = smem + 12352;            // [32 b][33]
    float* hst    = smem + 13408;            // [8 jj][32 b]  (this block's fp32 h)
    int*   lens_sm= (int*)(smem + 13664);    // [32]

    const int tid  = threadIdx.x;
    const int lane = tid & 31;
    const int warp = tid >> 5;
    const int blk = blockIdx.x;
    const int dir    = blk >> 6;
    const int jslice = (blk >> 1) & 31;
    const int bh     = blk & 1;
    const int j0 = jslice * 8;
    const int b0 = bh * 32;
    const int grp = dir * 2 + bh;
    const float* Whh = dir ? Whh_b : Whh_f;
    const float* xg  = dir ? xg_b  : xg_f;

    // warp mma coordinates
    const int mw  = warp & 1;
    const int nw2 = (warp >> 1) & 1;
    const int kh  = warp >> 2;
    const int lg  = lane >> 2;
    const int lc  = lane & 3;
    const int bcol0 = 16*nw2 + lg;
    const int khbase = kh * 128;

    // one-time Whh A-fragment load (resident all steps)
    uint32_t wfrag[16][4];
    #pragma unroll
    for (int ka = 0; ka < 16; ka++) {
        #pragma unroll
        for (int i = 0; i < 4; i++) {
            int r   = 16*mw + lg + (i & 1) * 8;
            int col = khbase + ka*8 + lc + (i >> 1) * 4;
            int g = r >> 3, jj = r & 7;
            wfrag[ka][i] = f2tf32(Whh[(size_t)(g*HID + j0 + jj) * HID + col]);
        }
    }
    if (tid < 32) lens_sm[tid] = lengths[b0 + tid];
    hst[tid] = 0.f;                      // h(s=0) = 0

    // xg staging mapping
    const int sb    = tid >> 3;
    const int sg    = (tid >> 1) & 3;
    const int shalf = tid & 1;
    const size_t xg_row_base = ((size_t)(b0 + sb) * SEQ);
    const int xg_col = sg*HID + j0 + shalf*4;

    // combine mapping
    const int rr = tid >> 5;
    const int cb = tid & 31;
    float c_reg = 0.f;

    __syncthreads();

    // group max length (uniform across the 32 blocks of this group)
    int maxlen = 0;
    #pragma unroll 8
    for (int i = 0; i < 32; i++) maxlen = max(maxlen, lens_sm[i]);
    const int S1 = maxlen;          // fwd: real steps s in [0, S1)
    const int S0 = SEQ - maxlen;    // bwd: real steps s in [S0, SEQ)

    // prologue xg prefetch for the first REAL step
    const int s_first = dir ? S0 : 0;
    float4 xg_pf = make_float4(0.f,0.f,0.f,0.f);
    if (s_first < SEQ && maxlen > 0) {
        int tf = dir ? (SEQ - 1 - s_first) : 0;
        xg_pf = __ldg((const float4*)(xg + (xg_row_base + tf) * G4 + xg_col));
    }

    for (int s = 0; s < SEQ; s++) {
        const int t = dir ? (SEQ - 1 - s) : s;
        const bool real = dir ? (s >= S0) : (s < S1);

        if (real) {
            const bool need_poll = dir ? (s > S0) : (s > 0);
            if (need_poll) {
                if (tid == 0) {
                    int* cnt = bar + ((s-1)*4 + grp)*8;
                    while (ld_acquire(cnt) < GRP_BLOCKS) __nanosleep(40);
                }
                __syncthreads();
            }

            // stage xg + h (raw fp32; mma truncates to tf32) + prefetch next xg
            {
                float* xd = xg_sm + sb*33 + sg*8 + shalf*4;
                xd[0] = xg_pf.x; xd[1] = xg_pf.y; xd[2] = xg_pf.z; xd[3] = xg_pf.w;

                const float* hsrc = hbuf + (size_t)((s & 1)*2 + dir) * HID * BATCH;
                #pragma unroll
                for (int n = 0; n < 8; n++) {
                    int i = tid + n*256;                 // 0..2047
                    int k = i >> 3, o = (i & 7)*4;
                    float4 v = __ldcg((const float4*)(hsrc + k*BATCH + b0 + o));
                    *(float4*)(ht + k*HSTRIDE + o) = v;
                }

                if (s + 1 < SEQ) {
                    int tn = dir ? (SEQ - 2 - s) : (s + 1);
                    xg_pf = __ldg((const float4*)(xg + (xg_row_base + tn) * G4 + xg_col));
                }
            }
            __syncthreads();

            // tensor-core gate GEMM over this warp's k-half (B frags from smem)
            {
                float acc[2][4];
                #pragma unroll
                for (int na = 0; na < 2; na++)
                    #pragma unroll
                    for (int r = 0; r < 4; r++) acc[na][r] = 0.f;

                #pragma unroll
                for (int ka = 0; ka < 16; ka++) {
                    const float* hp = ht + (khbase + ka*8 + lc)*HSTRIDE;
                    #pragma unroll
                    for (int na = 0; na < 2; na++) {
                        const int bc = bcol0 + na*8;
                        uint32_t bf0 = __float_as_uint(hp[bc]);
                        uint32_t bf1 = __float_as_uint(hp[4*HSTRIDE + bc]);
                        mma_tf32(acc[na][0], acc[na][1], acc[na][2], acc[na][3],
                                 wfrag[ka][0], wfrag[ka][1], wfrag[ka][2], wfrag[ka][3],
                                 bf0, bf1);
                    }
                }

                float* pd = part + kh*1056;
                #pragma unroll
                for (int na = 0; na < 2; na++) {
                    int col = 16*nw2 + na*8 + 2*lc;
                    int row = 16*mw + lg;
                    pd[row*33 + col]         = acc[na][0];
                    pd[row*33 + col + 1]     = acc[na][1];
                    pd[(row + 8)*33 + col]   = acc[na][2];
                    pd[(row + 8)*33 + col+1] = acc[na][3];
                }
            }
            __syncthreads();

            // combine: thread = (jj=rr, b=cb); h_prev from our own previous hst (fp32-exact)
            {
                float gate[4];
                #pragma unroll
                for (int g = 0; g < 4; g++) {
                    int r = g*8 + rr;
                    gate[g] = part[r*33 + cb] + part[1056 + r*33 + cb]
                            + xg_sm[cb*33 + g*8 + rr];
                }
                float h_prev = hst[rr*32 + cb];
                float c_new = sigf(gate[1]) * c_reg + sigf(gate[0]) * tanhf_(gate[2]);
                float h_new = sigf(gate[3]) * tanhf_(c_new);
                bool  m = (t < lens_sm[cb]);
                float h_out = m ? h_new : h_prev;
                c_reg       = m ? c_new : c_reg;

                hbuf[(size_t)(((s+1) & 1)*2 + dir) * HID * BATCH + (j0 + rr)*BATCH + b0 + cb] = h_out;
                hst[rr*32 + cb] = h_out;
            }
            __syncthreads();
            if (tid == 0) red_release_add(bar + (s*4 + grp)*8, 1);
        }

        // out store every step (hst frozen during skip steps)
        if (tid < 64) {
            int bb  = tid >> 1;
            int seg = tid & 1;
            float4 v;
            v.x = hst[(seg*4+0)*32 + bb];
            v.y = hst[(seg*4+1)*32 + bb];
            v.z = hst[(seg*4+2)*32 + bb];
            v.w = hst[(seg*4+3)*32 + bb];
            *(float4*)(out + ((size_t)(b0 + bb) * SEQ + t) * (2*HID) + dir*HID + j0 + seg*4) = v;
        }
    }
}

// ---------------- launch ----------------
extern "C" void kernel_launch(void* const* d_in, const int* in_sizes, int n_in,
                              void* d_out, int out_size)
{
    (void)in_sizes; (void)n_in; (void)out_size;
    const int*   words    = (const int*)  d_in[0];
    const int*   lengths  = (const int*)  d_in[1];
    const float* emb      = (const float*)d_in[2];
    const float* l1f_Wih  = (const float*)d_in[3];
    const float* l1f_Whh  = (const float*)d_in[4];
    const float* l1f_bih  = (const float*)d_in[5];
    const float* l1f_bhh  = (const float*)d_in[6];
    const float* l1b_Wih  = (const float*)d_in[7];
    const float* l1b_Whh  = (const float*)d_in[8];
    const float* l1b_bih  = (const float*)d_in[9];
    const float* l1b_bhh  = (const float*)d_in[10];
    const float* l2f_Wih  = (const float*)d_in[11];
    const float* l2f_Whh  = (const float*)d_in[12];
    const float* l2f_bih  = (const float*)d_in[13];
    const float* l2f_bhh  = (const float*)d_in[14];
    const float* l2b_Wih  = (const float*)d_in[15];
    const float* l2b_Whh  = (const float*)d_in[16];
    const float* l2b_bih  = (const float*)d_in[17];
    const float* l2b_bhh  = (const float*)d_in[18];
    const float* cls_W    = (const float*)d_in[19];
    const float* cls_b    = (const float*)d_in[20];
    float* out = (float*)d_out;

    float *px, *pxf, *pxb, *po1, *po2, *ph1, *ph2;
    int *pbar;
    cudaGetSymbolAddress((void**)&px,   g_x);
    cudaGetSymbolAddress((void**)&pxf,  g_xg_f);
    cudaGetSymbolAddress((void**)&pxb,  g_xg_b);
    cudaGetSymbolAddress((void**)&po1,  g_o1);
    cudaGetSymbolAddress((void**)&po2,  g_o2);
    cudaGetSymbolAddress((void**)&ph1,  g_h1);
    cudaGetSymbolAddress((void**)&ph2,  g_h2);
    cudaGetSymbolAddress((void**)&pbar, g_bar);

    cudaFuncSetAttribute(recur_kernel, cudaFuncAttributeMaxDynamicSharedMemorySize, SMEM_RECUR);

    // 1) init
    init_kernel<<<256, 256>>>();

    // 2) embedding
    embed_kernel<<<M_ROWS/8, 256>>>(words, emb);

    // 3) layer-1 input projections
    dim3 gx(G4/128, M_ROWS/128, 2);
    gemm_tf32_dual<<<gx, 256>>>(px, l1f_Wih, l1b_Wih,
                                l1f_bih, l1f_bhh, l1b_bih, l1b_bhh,
                                pxf, pxb, M_ROWS, G4, EMB);

    // 4) layer-1 recurrence
    recur_kernel<<<REC_BLOCKS, 256, SMEM_RECUR>>>(pxf, pxb, l1f_Whh, l1b_Whh,
                                                  lengths, po1, ph1, pbar);

    // 5) layer-2 input projections
    gemm_tf32_dual<<<gx, 256>>>(po1, l2f_Wih, l2b_Wih,
                                l2f_bih, l2f_bhh, l2b_bih, l2b_bhh,
                                pxf, pxb, M_ROWS, G4, 2*HID);

    // 6) layer-2 recurrence
    recur_kernel<<<REC_BLOCKS, 256, SMEM_RECUR>>>(pxf, pxb, l2f_Whh, l2b_Whh,
                                                  lengths, po2, ph2, pbar + SEQ*4*8);

    // 7) classifier (tf32 tensor cores, N guarded)
    dim3 gc(1, M_ROWS/128, 1);
    gemm_tf32_cls<<<gc, 256>>>(po2, cls_W, cls_b, out, M_ROWS, NTAGS, 2*HID);
}

// round 17
// speedup vs baseline: 1.4605x; 1.0025x over previous
#include <cuda_runtime.h>
#include <cstdint>

#define BATCH 64
#define SEQ   512
#define EMB   128
#define HID   256
#define G4    1024            // 4*HID
#define NTAGS 50
#define M_ROWS (BATCH*SEQ)    // 32768
#define REC_BLOCKS 128        // 2 dirs * 16 j-slices * 4 batch-quarters
#define GRP_BLOCKS 16         // blocks per (dir, bquarter) barrier group
#define NGRP 8                // barrier groups
#define HTS 24                // ht smem row stride (floats), conflict-free B frags

// ---------------- scratch (device globals; allocation-free) ----------------
__device__ float g_x   [(size_t)M_ROWS*EMB];
__device__ float g_xg_f[(size_t)M_ROWS*G4];
__device__ float g_xg_b[(size_t)M_ROWS*G4];
__device__ float g_o1  [(size_t)M_ROWS*2*HID];
__device__ float g_o2  [(size_t)M_ROWS*2*HID];
__device__ float g_h1  [2][2][HID][BATCH];        // [parity][dir][k][b]
__device__ float g_h2  [2][2][HID][BATCH];
__device__ int   g_bar [2][SEQ][NGRP][8];         // [layer][step][group][pad]

// ---------------- helpers ----------------
__device__ __forceinline__ int ld_acquire(const int* p) {
    int v;
    asm volatile("ld.global.acquire.gpu.b32 %0, [%1];" : "=r"(v) : "l"(p));
    return v;
}
__device__ __forceinline__ void red_release_add(int* p, int v) {
    asm volatile("red.release.gpu.global.add.u32 [%0], %1;" :: "l"(p), "r"(v) : "memory");
}
__device__ __forceinline__ float sigf(float x)  { return 1.f/(1.f + __expf(-x)); }
__device__ __forceinline__ float tanhf_(float x){ return 1.f - 2.f/(__expf(2.f*x) + 1.f); }
__device__ __forceinline__ uint32_t f2tf32(float f) {
    uint32_t u;
    asm("cvt.rna.tf32.f32 %0, %1;" : "=r"(u) : "f"(f));
    return u;
}
__device__ __forceinline__ void mma_tf32(float& c0, float& c1, float& c2, float& c3,
                                         uint32_t a0, uint32_t a1, uint32_t a2, uint32_t a3,
                                         uint32_t b0, uint32_t b1) {
    asm volatile("mma.sync.aligned.m16n8k8.row.col.f32.tf32.tf32.f32 "
                 "{%0,%1,%2,%3}, {%4,%5,%6,%7}, {%8,%9}, {%0,%1,%2,%3};"
                 : "+f"(c0), "+f"(c1), "+f"(c2), "+f"(c3)
                 : "r"(a0), "r"(a1), "r"(a2), "r"(a3), "r"(b0), "r"(b1));
}

// ---------------- init ----------------
__global__ void init_kernel() {
    int i = blockIdx.x * blockDim.x + threadIdx.x;    // 65536 threads
    if (i < 2*2*HID*BATCH) {
        (&g_h1[0][0][0][0])[i] = 0.f;
        (&g_h2[0][0][0][0])[i] = 0.f;
    }
    if (i < 2*SEQ*NGRP*8) (&g_bar[0][0][0][0])[i] = 0;
}

// ---------------- embedding ----------------
__global__ void embed_kernel(const int* __restrict__ words, const float* __restrict__ emb) {
    int row = blockIdx.x * 8 + (threadIdx.x >> 5);
    int lane = threadIdx.x & 31;
    int w = words[row];
    const float4* src = (const float4*)(emb + (size_t)w * EMB);
    float4*       dst = (float4*)(g_x + (size_t)row * EMB);
    dst[lane] = src[lane];
}

// ---------------- tf32 tensor-core dual GEMM (unchanged) ----------------
__global__ __launch_bounds__(256) void gemm_tf32_dual(
    const float* __restrict__ A,
    const float* __restrict__ Bw_f, const float* __restrict__ Bw_b,
    const float* __restrict__ b1f, const float* __restrict__ b2f,
    const float* __restrict__ b1b, const float* __restrict__ b2b,
    float* __restrict__ Cf, float* __restrict__ Cb,
    int M, int N, int K)
{
    const float* Bw    = blockIdx.z ? Bw_b : Bw_f;
    const float* bias1 = blockIdx.z ? b1b  : b1f;
    const float* bias2 = blockIdx.z ? b2b  : b2f;
    float*       C     = blockIdx.z ? Cb   : Cf;

    __shared__ uint32_t As[2][128][20];
    __shared__ uint32_t Bs[2][128][20];

    const int tid  = threadIdx.x;
    const int lane = tid & 31;
    const int warp = tid >> 5;
    const int m0 = blockIdx.y * 128;
    const int n0 = blockIdx.x * 128;
    const int wm = (warp >> 2) * 64;
    const int wn = (warp & 3) * 32;
    const int ar = lane >> 2;
    const int ac = lane & 3;

    const int lr = tid >> 2;
    const int lk = (tid & 3) * 4;
    const float* Aptr0 = A  + (size_t)(m0 + lr)      * K + lk;
    const float* Aptr1 = A  + (size_t)(m0 + 64 + lr) * K + lk;
    const float* Bptr0 = Bw + (size_t)(n0 + lr)      * K + lk;
    const float* Bptr1 = Bw + (size_t)(n0 + 64 + lr) * K + lk;

    float c[4][4][4];
    #pragma unroll
    for (int i = 0; i < 4; i++)
        #pragma unroll
        for (int j = 0; j < 4; j++)
            #pragma unroll
            for (int r = 0; r < 4; r++) c[i][j][r] = 0.f;

    {
        float4 a0 = *(const float4*)Aptr0;
        float4 a1 = *(const float4*)Aptr1;
        float4 b0 = *(const float4*)Bptr0;
        float4 b1 = *(const float4*)Bptr1;
        As[0][lr][lk+0]=f2tf32(a0.x); As[0][lr][lk+1]=f2tf32(a0.y); As[0][lr][lk+2]=f2tf32(a0.z); As[0][lr][lk+3]=f2tf32(a0.w);
        As[0][64+lr][lk+0]=f2tf32(a1.x); As[0][64+lr][lk+1]=f2tf32(a1.y); As[0][64+lr][lk+2]=f2tf32(a1.z); As[0][64+lr][lk+3]=f2tf32(a1.w);
        Bs[0][lr][lk+0]=f2tf32(b0.x); Bs[0][lr][lk+1]=f2tf32(b0.y); Bs[0][lr][lk+2]=f2tf32(b0.z); Bs[0][lr][lk+3]=f2tf32(b0.w);
        Bs[0][64+lr][lk+0]=f2tf32(b1.x); Bs[0][64+lr][lk+1]=f2tf32(b1.y); Bs[0][64+lr][lk+2]=f2tf32(b1.z); Bs[0][64+lr][lk+3]=f2tf32(b1.w);
    }
    __syncthreads();

    const int T = K / 16;
    float4 pa0, pa1, pb0, pb1;
    for (int tI = 0; tI < T; tI++) {
        const int buf = tI & 1;
        const bool more = (tI + 1 < T);
        if (more) {
            const int off = (tI + 1) * 16;
            pa0 = *(const float4*)(Aptr0 + off);
            pa1 = *(const float4*)(Aptr1 + off);
            pb0 = *(const float4*)(Bptr0 + off);
            pb1 = *(const float4*)(Bptr1 + off);
        }

        #pragma unroll
        for (int kb = 0; kb < 16; kb += 8) {
            uint32_t afr[4][4];
            #pragma unroll
            for (int i = 0; i < 4; i++) {
                int mrow = wm + i*16 + ar;
                afr[i][0] = As[buf][mrow    ][kb + ac];
                afr[i][1] = As[buf][mrow + 8][kb + ac];
                afr[i][2] = As[buf][mrow    ][kb + ac + 4];
                afr[i][3] = As[buf][mrow + 8][kb + ac + 4];
            }
            uint32_t bfr[4][2];
            #pragma unroll
            for (int j = 0; j < 4; j++) {
                int nrow = wn + j*8 + ar;
                bfr[j][0] = Bs[buf][nrow][kb + ac];
                bfr[j][1] = Bs[buf][nrow][kb + ac + 4];
            }
            #pragma unroll
            for (int i = 0; i < 4; i++)
                #pragma unroll
                for (int j = 0; j < 4; j++)
                    mma_tf32(c[i][j][0], c[i][j][1], c[i][j][2], c[i][j][3],
                             afr[i][0], afr[i][1], afr[i][2], afr[i][3],
                             bfr[j][0], bfr[j][1]);
        }

        if (more) {
            const int nb = buf ^ 1;
            __syncthreads();
            As[nb][lr][lk+0]=f2tf32(pa0.x); As[nb][lr][lk+1]=f2tf32(pa0.y); As[nb][lr][lk+2]=f2tf32(pa0.z); As[nb][lr][lk+3]=f2tf32(pa0.w);
            As[nb][64+lr][lk+0]=f2tf32(pa1.x); As[nb][64+lr][lk+1]=f2tf32(pa1.y); As[nb][64+lr][lk+2]=f2tf32(pa1.z); As[nb][64+lr][lk+3]=f2tf32(pa1.w);
            Bs[nb][lr][lk+0]=f2tf32(pb0.x); Bs[nb][lr][lk+1]=f2tf32(pb0.y); Bs[nb][lr][lk+2]=f2tf32(pb0.z); Bs[nb][lr][lk+3]=f2tf32(pb0.w);
            Bs[nb][64+lr][lk+0]=f2tf32(pb1.x); Bs[nb][64+lr][lk+1]=f2tf32(pb1.y); Bs[nb][64+lr][lk+2]=f2tf32(pb1.z); Bs[nb][64+lr][lk+3]=f2tf32(pb1.w);
            __syncthreads();
        }
    }

    #pragma unroll
    for (int i = 0; i < 4; i++) {
        int row0 = m0 + wm + i*16 + ar;
        #pragma unroll
        for (int j = 0; j < 4; j++) {
            int col = n0 + wn + j*8 + 2*ac;
            float bsum0 = bias1[col]   + (bias2 ? bias2[col]   : 0.f);
            float bsum1 = bias1[col+1] + (bias2 ? bias2[col+1] : 0.f);
            *(float2*)(C + (size_t)row0 * N + col)       = make_float2(c[i][j][0] + bsum0, c[i][j][1] + bsum1);
            *(float2*)(C + (size_t)(row0 + 8) * N + col) = make_float2(c[i][j][2] + bsum0, c[i][j][3] + bsum1);
        }
    }
}

// ---------------- tf32 tensor-core classifier GEMM (N=50 guarded, unchanged) ----------------
__global__ __launch_bounds__(256) void gemm_tf32_cls(
    const float* __restrict__ A, const float* __restrict__ Bw,
    const float* __restrict__ bias1,
    float* __restrict__ C, int M, int N, int K)
{
    __shared__ uint32_t As[2][128][20];
    __shared__ uint32_t Bs[2][128][20];

    const int tid  = threadIdx.x;
    const int lane = tid & 31;
    const int warp = tid >> 5;
    const int m0 = blockIdx.y * 128;
    const int wm = (warp >> 2) * 64;
    const int wn = (warp & 3) * 32;
    const int ar = lane >> 2;
    const int ac = lane & 3;

    const int lr = tid >> 2;
    const int lk = (tid & 3) * 4;
    const float* Aptr0 = A  + (size_t)(m0 + lr)      * K + lk;
    const float* Aptr1 = A  + (size_t)(m0 + 64 + lr) * K + lk;
    const bool b0ok = lr < N;
    const bool b1ok = (64 + lr) < N;
    const float* Bptr0 = Bw + (size_t)lr        * K + lk;
    const float* Bptr1 = Bw + (size_t)(64 + lr) * K + lk;
    const float4 z4 = make_float4(0.f,0.f,0.f,0.f);

    float c[4][4][4];
    #pragma unroll
    for (int i = 0; i < 4; i++)
        #pragma unroll
        for (int j = 0; j < 4; j++)
            #pragma unroll
            for (int r = 0; r < 4; r++) c[i][j][r] = 0.f;

    {
        float4 a0 = *(const float4*)Aptr0;
        float4 a1 = *(const float4*)Aptr1;
        float4 b0 = b0ok ? *(const float4*)Bptr0 : z4;
        float4 b1 = b1ok ? *(const float4*)Bptr1 : z4;
        As[0][lr][lk+0]=f2tf32(a0.x); As[0][lr][lk+1]=f2tf32(a0.y); As[0][lr][lk+2]=f2tf32(a0.z); As[0][lr][lk+3]=f2tf32(a0.w);
        As[0][64+lr][lk+0]=f2tf32(a1.x); As[0][64+lr][lk+1]=f2tf32(a1.y); As[0][64+lr][lk+2]=f2tf32(a1.z); As[0][64+lr][lk+3]=f2tf32(a1.w);
        Bs[0][lr][lk+0]=f2tf32(b0.x); Bs[0][lr][lk+1]=f2tf32(b0.y); Bs[0][lr][lk+2]=f2tf32(b0.z); Bs[0][lr][lk+3]=f2tf32(b0.w);
        Bs[0][64+lr][lk+0]=f2tf32(b1.x); Bs[0][64+lr][lk+1]=f2tf32(b1.y); Bs[0][64+lr][lk+2]=f2tf32(b1.z); Bs[0][64+lr][lk+3]=f2tf32(b1.w);
    }
    __syncthreads();

    const int T = K / 16;
    float4 pa0, pa1, pb0, pb1;
    for (int tI = 0; tI < T; tI++) {
        const int buf = tI & 1;
        const bool more = (tI + 1 < T);
        if (more) {
            const int off = (tI + 1) * 16;
            pa0 = *(const float4*)(Aptr0 + off);
            pa1 = *(const float4*)(Aptr1 + off);
            pb0 = b0ok ? *(const float4*)(Bptr0 + off) : z4;
            pb1 = b1ok ? *(const float4*)(Bptr1 + off) : z4;
        }

        #pragma unroll
        for (int kb = 0; kb < 16; kb += 8) {
            uint32_t afr[4][4];
            #pragma unroll
            for (int i = 0; i < 4; i++) {
                int mrow = wm + i*16 + ar;
                afr[i][0] = As[buf][mrow    ][kb + ac];
                afr[i][1] = As[buf][mrow + 8][kb + ac];
                afr[i][2] = As[buf][mrow    ][kb + ac + 4];
                afr[i][3] = As[buf][mrow + 8][kb + ac + 4];
            }
            uint32_t bfr[4][2];
            #pragma unroll
            for (int j = 0; j < 4; j++) {
                int nrow = wn + j*8 + ar;
                bfr[j][0] = Bs[buf][nrow][kb + ac];
                bfr[j][1] = Bs[buf][nrow][kb + ac + 4];
            }
            #pragma unroll
            for (int i = 0; i < 4; i++)
                #pragma unroll
                for (int j = 0; j < 4; j++)
                    mma_tf32(c[i][j][0], c[i][j][1], c[i][j][2], c[i][j][3],
                             afr[i][0], afr[i][1], afr[i][2], afr[i][3],
                             bfr[j][0], bfr[j][1]);
        }

        if (more) {
            const int nb = buf ^ 1;
            __syncthreads();
            As[nb][lr][lk+0]=f2tf32(pa0.x); As[nb][lr][lk+1]=f2tf32(pa0.y); As[nb][lr][lk+2]=f2tf32(pa0.z); As[nb][lr][lk+3]=f2tf32(pa0.w);
            As[nb][64+lr][lk+0]=f2tf32(pa1.x); As[nb][64+lr][lk+1]=f2tf32(pa1.y); As[nb][64+lr][lk+2]=f2tf32(pa1.z); As[nb][64+lr][lk+3]=f2tf32(pa1.w);
            Bs[nb][lr][lk+0]=f2tf32(pb0.x); Bs[nb][lr][lk+1]=f2tf32(pb0.y); Bs[nb][lr][lk+2]=f2tf32(pb0.z); Bs[nb][lr][lk+3]=f2tf32(pb0.w);
            Bs[nb][64+lr][lk+0]=f2tf32(pb1.x); Bs[nb][64+lr][lk+1]=f2tf32(pb1.y); Bs[nb][64+lr][lk+2]=f2tf32(pb1.z); Bs[nb][64+lr][lk+3]=f2tf32(pb1.w);
            __syncthreads();
        }
    }

    #pragma unroll
    for (int i = 0; i < 4; i++) {
        int row0 = m0 + wm + i*16 + ar;
        #pragma unroll
        for (int j = 0; j < 4; j++) {
            int col = wn + j*8 + 2*ac;
            if (col < N) {
                float bsum0 = bias1[col];
                float bsum1 = bias1[col+1];
                *(float2*)(C + (size_t)row0 * N + col)       = make_float2(c[i][j][0] + bsum0, c[i][j][1] + bsum1);
                *(float2*)(C + (size_t)(row0 + 8) * N + col) = make_float2(c[i][j][2] + bsum0, c[i][j][3] + bsum1);
            }
        }
    }
}

// ---------------- persistent BiLSTM recurrence: 16j x 16b tiles, 16-block groups -----------
// 128 blocks = dir(2) x jslice(16, 16 j each) x bquarter(4, 16 b each); 256 threads.
// Warp w: mt=w&3 (16-row m-tile of 64 gate rows), kh=w>>2 (128-k half); both n-atoms.
// Whh resident in regs (64/thread). h staged per step (4 float4/thread) as raw fp32.
// Fully-masked steps (t >= group max length) skip barrier/stage/mma.
// SMEM floats: ht 256*24=6144, part 2*64*17=2176, xg 16*65=1040, hst 256, lens 16 = 9632
#define SMEM_RECUR (9632 * 4)

__global__ __launch_bounds__(256, 1) void recur_kernel(
    const float* __restrict__ xg_f, const float* __restrict__ xg_b,
    const float* __restrict__ Whh_f, const float* __restrict__ Whh_b,
    const int* __restrict__ lengths, float* __restrict__ out,
    float* __restrict__ hbuf, int* __restrict__ bar)
{
    extern __shared__ float smem[];
    float* ht     = smem;                    // [256 k][24]
    float* part   = smem + 6144;             // [2 kh][64 r][17]
    float* xg_sm  = smem + 8320;             // [16 b][65]  (4g x 16j packed in 64, pad 1)
    float* hst    = smem + 9360;             // [16 jj][16 b]
    int*   lens_sm= (int*)(smem + 9616);     // [16]

    const int tid  = threadIdx.x;
    const int lane = tid & 31;
    const int warp = tid >> 5;
    const int blk = blockIdx.x;
    const int dir    = blk >> 6;             // 0..1
    const int jslice = (blk >> 2) & 15;      // 0..15  (16 j's each)
    const int bq     = blk & 3;              // 0..3   (16 b each)
    const int j0 = jslice * 16;
    const int b0 = bq * 16;
    const int grp = dir * 4 + bq;            // 0..7
    const float* Whh = dir ? Whh_b : Whh_f;
    const float* xg  = dir ? xg_b  : xg_f;

    // warp mma coordinates
    const int mt  = warp & 3;                // m-tile (local rows mt*16 .. +15)
    const int kh  = warp >> 2;               // k half
    const int lg  = lane >> 2;               // 0..7
    const int lc  = lane & 3;                // 0..3
    const int khbase = kh * 128;

    // one-time Whh A-fragment load (resident all steps)
    uint32_t wfrag[16][4];
    #pragma unroll
    for (int ka = 0; ka < 16; ka++) {
        #pragma unroll
        for (int i = 0; i < 4; i++) {
            int r   = mt*16 + lg + (i & 1) * 8;          // local row 0..63 = g*16+jj
            int col = khbase + ka*8 + lc + (i >> 1) * 4;
            int g = r >> 4, jj = r & 15;
            wfrag[ka][i] = f2tf32(Whh[(size_t)(g*HID + j0 + jj) * HID + col]);
        }
    }
    if (tid < 16) lens_sm[tid] = lengths[b0 + tid];
    hst[tid] = 0.f;                      // covers all 256 entries (16x16)

    // xg staging mapping: thread -> one float4/step
    const int sb = tid >> 4;             // 0..15 batch
    const int sg = (tid >> 2) & 3;       // gate
    const int sq = tid & 3;              // j quarter
    const size_t xg_row_base = ((size_t)(b0 + sb) * SEQ);
    const int xg_col = sg*HID + j0 + sq*4;

    // combine mapping: thread -> (jj, b)
    const int rr = tid >> 4;             // jj 0..15
    const int cb = tid & 15;             // b  0..15
    float c_reg = 0.f;

    __syncthreads();

    // group max length (uniform across the 16 blocks of this group)
    int maxlen = 0;
    #pragma unroll
    for (int i = 0; i < 16; i++) maxlen = max(maxlen, lens_sm[i]);
    const int S1 = maxlen;
    const int S0 = SEQ - maxlen;

    // prologue xg prefetch for the first REAL step
    const int s_first = dir ? S0 : 0;
    float4 xg_pf = make_float4(0.f,0.f,0.f,0.f);
    if (s_first < SEQ && maxlen > 0) {
        int tf = dir ? (SEQ - 1 - s_first) : 0;
        xg_pf = __ldg((const float4*)(xg + (xg_row_base + tf) * G4 + xg_col));
    }

    for (int s = 0; s < SEQ; s++) {
        const int t = dir ? (SEQ - 1 - s) : s;
        const bool real = dir ? (s >= S0) : (s < S1);

        if (real) {
            const bool need_poll = dir ? (s > S0) : (s > 0);
            if (need_poll) {
                if (tid == 0) {
                    int* cnt = bar + ((s-1)*NGRP + grp)*8;
                    while (ld_acquire(cnt) < GRP_BLOCKS) __nanosleep(40);
                }
                __syncthreads();
            }

            // stage xg + h (raw fp32; mma truncates) + prefetch next xg
            {
                float* xd = xg_sm + sb*65 + sg*16 + sq*4;
                xd[0] = xg_pf.x; xd[1] = xg_pf.y; xd[2] = xg_pf.z; xd[3] = xg_pf.w;

                const float* hsrc = hbuf + (size_t)((s & 1)*2 + dir) * HID * BATCH;
                #pragma unroll
                for (int n = 0; n < 4; n++) {
                    int i = tid + n*256;                 // 0..1023
                    int k = i >> 2, o = (i & 3)*4;       // k 0..255, o 0,4,8,12
                    float4 v = __ldcg((const float4*)(hsrc + k*BATCH + b0 + o));
                    *(float4*)(ht + k*HTS + o) = v;
                }

                if (s + 1 < SEQ) {
                    int tn = dir ? (SEQ - 2 - s) : (s + 1);
                    xg_pf = __ldg((const float4*)(xg + (xg_row_base + tn) * G4 + xg_col));
                }
            }
            __syncthreads();

            // tensor-core gate GEMM over this warp's k-half (B frags from smem)
            {
                float acc[2][4];
                #pragma unroll
                for (int na = 0; na < 2; na++)
                    #pragma unroll
                    for (int r = 0; r < 4; r++) acc[na][r] = 0.f;

                #pragma unroll
                for (int ka = 0; ka < 16; ka++) {
                    const float* hp = ht + (khbase + ka*8 + lc)*HTS;
                    #pragma unroll
                    for (int na = 0; na < 2; na++) {
                        const int bc = na*8 + lg;
                        uint32_t bf0 = __float_as_uint(hp[bc]);
                        uint32_t bf1 = __float_as_uint(hp[4*HTS + bc]);
                        mma_tf32(acc[na][0], acc[na][1], acc[na][2], acc[na][3],
                                 wfrag[ka][0], wfrag[ka][1], wfrag[ka][2], wfrag[ka][3],
                                 bf0, bf1);
                    }
                }

                float* pd = part + kh*1088;              // 64*17
                #pragma unroll
                for (int na = 0; na < 2; na++) {
                    int col = na*8 + 2*lc;
                    int row = mt*16 + lg;
                    pd[row*17 + col]         = acc[na][0];
                    pd[row*17 + col + 1]     = acc[na][1];
                    pd[(row + 8)*17 + col]   = acc[na][2];
                    pd[(row + 8)*17 + col+1] = acc[na][3];
                }
            }
            __syncthreads();

            // combine: thread = (jj=rr, b=cb); h_prev from our own previous hst (fp32-exact)
            {
                float gate[4];
                #pragma unroll
                for (int g = 0; g < 4; g++) {
                    int r = g*16 + rr;
                    gate[g] = part[r*17 + cb] + part[1088 + r*17 + cb]
                            + xg_sm[cb*65 + g*16 + rr];
                }
                float h_prev = hst[rr*16 + cb];
                float c_new = sigf(gate[1]) * c_reg + sigf(gate[0]) * tanhf_(gate[2]);
                float h_new = sigf(gate[3]) * tanhf_(c_new);
                bool  m = (t < lens_sm[cb]);
                float h_out = m ? h_new : h_prev;
                c_reg       = m ? c_new : c_reg;

                hbuf[(size_t)(((s+1) & 1)*2 + dir) * HID * BATCH + (j0 + rr)*BATCH + b0 + cb] = h_out;
                hst[rr*16 + cb] = h_out;
            }
            __syncthreads();
            if (tid == 0) red_release_add(bar + (s*NGRP + grp)*8, 1);
        }

        // out store every step (hst frozen during skip steps): 64 threads x float4
        if (tid < 64) {
            int bb  = tid >> 2;          // 0..15
            int seg = tid & 3;           // 0..3
            float4 v;
            v.x = hst[(seg*4+0)*16 + bb];
            v.y = hst[(seg*4+1)*16 + bb];
            v.z = hst[(seg*4+2)*16 + bb];
            v.w = hst[(seg*4+3)*16 + bb];
            *(float4*)(out + ((size_t)(b0 + bb) * SEQ + t) * (2*HID) + dir*HID + j0 + seg*4) = v;
        }
    }
}

// ---------------- launch ----------------
extern "C" void kernel_launch(void* const* d_in, const int* in_sizes, int n_in,
                              void* d_out, int out_size)
{
    (void)in_sizes; (void)n_in; (void)out_size;
    const int*   words    = (const int*)  d_in[0];
    const int*   lengths  = (const int*)  d_in[1];
    const float* emb      = (const float*)d_in[2];
    const float* l1f_Wih  = (const float*)d_in[3];
    const float* l1f_Whh  = (const float*)d_in[4];
    const float* l1f_bih  = (const float*)d_in[5];
    const float* l1f_bhh  = (const float*)d_in[6];
    const float* l1b_Wih  = (const float*)d_in[7];
    const float* l1b_Whh  = (const float*)d_in[8];
    const float* l1b_bih  = (const float*)d_in[9];
    const float* l1b_bhh  = (const float*)d_in[10];
    const float* l2f_Wih  = (const float*)d_in[11];
    const float* l2f_Whh  = (const float*)d_in[12];
    const float* l2f_bih  = (const float*)d_in[13];
    const float* l2f_bhh  = (const float*)d_in[14];
    const float* l2b_Wih  = (const float*)d_in[15];
    const float* l2b_Whh  = (const float*)d_in[16];
    const float* l2b_bih  = (const float*)d_in[17];
    const float* l2b_bhh  = (const float*)d_in[18];
    const float* cls_W    = (const float*)d_in[19];
    const float* cls_b    = (const float*)d_in[20];
    float* out = (float*)d_out;

    float *px, *pxf, *pxb, *po1, *po2, *ph1, *ph2;
    int *pbar;
    cudaGetSymbolAddress((void**)&px,   g_x);
    cudaGetSymbolAddress((void**)&pxf,  g_xg_f);
    cudaGetSymbolAddress((void**)&pxb,  g_xg_b);
    cudaGetSymbolAddress((void**)&po1,  g_o1);
    cudaGetSymbolAddress((void**)&po2,  g_o2);
    cudaGetSymbolAddress((void**)&ph1,  g_h1);
    cudaGetSymbolAddress((void**)&ph2,  g_h2);
    cudaGetSymbolAddress((void**)&pbar, g_bar);

    cudaFuncSetAttribute(recur_kernel, cudaFuncAttributeMaxDynamicSharedMemorySize, SMEM_RECUR);

    // 1) init
    init_kernel<<<256, 256>>>();

    // 2) embedding
    embed_kernel<<<M_ROWS/8, 256>>>(words, emb);

    // 3) layer-1 input projections
    dim3 gx(G4/128, M_ROWS/128, 2);
    gemm_tf32_dual<<<gx, 256>>>(px, l1f_Wih, l1b_Wih,
                                l1f_bih, l1f_bhh, l1b_bih, l1b_bhh,
                                pxf, pxb, M_ROWS, G4, EMB);

    // 4) layer-1 recurrence
    recur_kernel<<<REC_BLOCKS, 256, SMEM_RECUR>>>(pxf, pxb, l1f_Whh, l1b_Whh,
                                                  lengths, po1, ph1, pbar);

    // 5) layer-2 input projections
    gemm_tf32_dual<<<gx, 256>>>(po1, l2f_Wih, l2b_Wih,
                                l2f_bih, l2f_bhh, l2b_bih, l2b_bhh,
                                pxf, pxb, M_ROWS, G4, 2*HID);

    // 6) layer-2 recurrence
    recur_kernel<<<REC_BLOCKS, 256, SMEM_RECUR>>>(pxf, pxb, l2f_Whh, l2b_Whh,
                                                  lengths, po2, ph2, pbar + SEQ*NGRP*8);

    // 7) classifier (tf32 tensor cores, N guarded)
    dim3 gc(1, M_ROWS/128, 1);
    gemm_tf32_cls<<<gc, 256>>>(po2, cls_W, cls_b, out, M_ROWS, NTAGS, 2*HID);
}